// round 2
// baseline (speedup 1.0000x reference)
#include <cuda_runtime.h>
#include <math.h>

#define NN 100000
#define NE 1600000
#define CH 128          // channels = H*D
#define NH 4
#define HD 32
#define EPS 1e-5f

// ---------------- scratch (device globals; no allocation allowed) ----------------
__device__ __align__(128) float g_h[NN * CH];
__device__ __align__(128) float g_q[NN * CH];
__device__ __align__(128) float g_k[NN * CH];
__device__ __align__(128) float g_v[NN * CH];
__device__ __align__(128) float g_sk[NN * CH];   // skip, then conv (in-place)
__device__ __align__(128) float g_stats[4 * CH]; // sum, sumsq, scale, shift
__device__ int g_cnt[NN];
__device__ int g_rowptr[NN + 1];
__device__ int g_cursor[NN];
__device__ int g_esrc[NE];
__device__ int g_is64;

// ---------------- edge dtype detection ----------------
// Reference asks for jnp.int64 but JAX (x64 disabled) canonicalizes to int32.
// If the buffer is int32, interpreting pairs as int64 yields values >= 2^32
// (whenever the second int32 != 0), so 256 in-range samples => really int64.
__global__ void detect_k(const long long* __restrict__ ei) {
    if (threadIdx.x == 0) {
        int ok = 1;
        for (int i = 0; i < 256; i++) {
            long long v = ei[i];
            if (v < 0 || v >= NN) { ok = 0; break; }
        }
        g_is64 = ok;
    }
}

__device__ __forceinline__ int edge_at(const void* ei, int idx) {
    return g_is64 ? (int)((const long long*)ei)[idx] : ((const int*)ei)[idx];
}

// ---------------- init: zero accumulators ----------------
__global__ void init_k() {
    int i = blockIdx.x * blockDim.x + threadIdx.x;
    if (i < 2 * CH) g_stats[i] = 0.f;
    for (int j = i; j < NN; j += gridDim.x * blockDim.x) g_cnt[j] = 0;
}

// ---------------- batchnorm stats ----------------
__global__ void bn_stats_k(const float* __restrict__ x) {
    int c = threadIdx.x; // 128 threads
    float s = 0.f, sq = 0.f;
    for (int r = blockIdx.x; r < NN; r += gridDim.x) {
        float v = x[r * CH + c];
        s += v; sq += v * v;
    }
    atomicAdd(&g_stats[c], s);
    atomicAdd(&g_stats[CH + c], sq);
}

__global__ void bn_finalize_k(const float* __restrict__ gamma, const float* __restrict__ beta) {
    int c = threadIdx.x;
    float mean = g_stats[c] / (float)NN;
    float var = g_stats[CH + c] / (float)NN - mean * mean;
    float scale = gamma[c] * rsqrtf(var + EPS);
    g_stats[2 * CH + c] = scale;
    g_stats[3 * CH + c] = beta[c] - mean * scale;
}

// ---------------- h = relu(bn(x)) ----------------
__global__ void bn_apply_k(const float* __restrict__ x) {
    int i = blockIdx.x * blockDim.x + threadIdx.x; // float4 index
    if (i < NN * CH / 4) {
        float4 xv = ((const float4*)x)[i];
        int c4 = i & 31;
        float4 sc = ((const float4*)(g_stats + 2 * CH))[c4];
        float4 sh = ((const float4*)(g_stats + 3 * CH))[c4];
        float4 h;
        h.x = fmaxf(0.f, xv.x * sc.x + sh.x);
        h.y = fmaxf(0.f, xv.y * sc.y + sh.y);
        h.z = fmaxf(0.f, xv.z * sc.z + sh.z);
        h.w = fmaxf(0.f, xv.w * sc.w + sh.w);
        ((float4*)g_h)[i] = h;
    }
}

// ---------------- CSR build ----------------
__global__ void hist_k(const void* __restrict__ ei) {
    int e = blockIdx.x * blockDim.x + threadIdx.x;
    if (e < NE) {
        int d = edge_at(ei, NE + e);
        if (d >= 0 && d < NN) atomicAdd(&g_cnt[d], 1);
    }
}

__global__ void scan_k() {
    __shared__ int warpsum[32];
    __shared__ int s_carry;
    int t = threadIdx.x, lane = t & 31, wid = t >> 5;
    if (t == 0) s_carry = 0;
    __syncthreads();
    for (int base = 0; base < NN; base += 1024) {
        int v = (base + t < NN) ? g_cnt[base + t] : 0;
        int x = v;
        #pragma unroll
        for (int o = 1; o < 32; o <<= 1) {
            int y = __shfl_up_sync(0xffffffffu, x, o);
            if (lane >= o) x += y;
        }
        if (lane == 31) warpsum[wid] = x;
        __syncthreads();
        if (wid == 0) {
            int w = warpsum[lane];
            #pragma unroll
            for (int o = 1; o < 32; o <<= 1) {
                int y = __shfl_up_sync(0xffffffffu, w, o);
                if (lane >= o) w += y;
            }
            warpsum[lane] = w;
        }
        __syncthreads();
        int carry = s_carry;
        int prefix = (wid > 0) ? warpsum[wid - 1] : 0;
        int incl = x + prefix;
        int excl = incl - v + carry;
        if (base + t < NN) { g_rowptr[base + t] = excl; g_cursor[base + t] = excl; }
        __syncthreads();
        if (t == 1023) s_carry = carry + incl;
        __syncthreads();
    }
    if (t == 0) g_rowptr[NN] = s_carry;
}

__global__ void scatter_k(const void* __restrict__ ei) {
    int e = blockIdx.x * blockDim.x + threadIdx.x;
    if (e < NE) {
        int d = edge_at(ei, NE + e);
        int s = edge_at(ei, e);
        if (d >= 0 && d < NN && s >= 0 && s < NN) {
            int pos = atomicAdd(&g_cursor[d], 1);
            if (pos >= 0 && pos < NE) g_esrc[pos] = s;
        }
    }
}

// ---------------- tiled SGEMM: Out[M,128] = A[M,128] @ W[128,128] + bias (+resid) ----------------
template <bool RESID>
__device__ __forceinline__ void gemm_body(const float* __restrict__ A, const float* __restrict__ W,
                                          const float* __restrict__ bias, float* __restrict__ Out,
                                          const float* __restrict__ resid) {
    extern __shared__ float sm[];
    float* As = sm;              // [128][132] transposed: As[k][m]
    float* Ws = sm + 128 * 132;  // [128][128]
    int t = threadIdx.x;
    int row0 = blockIdx.x * 128;
    int lane = t & 31, wq = t >> 5;

    // load A tile transposed (lanes cover m -> conflict-free smem stores)
    #pragma unroll
    for (int i = 0; i < 16; i++) {
        int m = lane + ((i & 3) << 5);
        int kq = wq + ((i >> 2) << 3);
        int gr = row0 + m;
        float4 a = (gr < NN) ? ((const float4*)A)[gr * 32 + kq] : make_float4(0.f, 0.f, 0.f, 0.f);
        int k4 = kq * 4;
        As[(k4 + 0) * 132 + m] = a.x;
        As[(k4 + 1) * 132 + m] = a.y;
        As[(k4 + 2) * 132 + m] = a.z;
        As[(k4 + 3) * 132 + m] = a.w;
    }
    // load W tile
    #pragma unroll
    for (int i = 0; i < 16; i++) {
        int k = wq + (i << 3);
        ((float4*)Ws)[k * 32 + lane] = ((const float4*)W)[k * 32 + lane];
    }
    __syncthreads();

    int tx = t & 15, ty = t >> 4;
    int m0 = ty * 8, n0 = tx * 8;
    float acc[8][8];
    #pragma unroll
    for (int i = 0; i < 8; i++)
        #pragma unroll
        for (int j = 0; j < 8; j++) acc[i][j] = 0.f;

    #pragma unroll 8
    for (int k = 0; k < 128; k++) {
        float a[8], b[8];
        *(float4*)(a)     = *(float4*)&As[k * 132 + m0];
        *(float4*)(a + 4) = *(float4*)&As[k * 132 + m0 + 4];
        *(float4*)(b)     = *(float4*)&Ws[k * 128 + n0];
        *(float4*)(b + 4) = *(float4*)&Ws[k * 128 + n0 + 4];
        #pragma unroll
        for (int i = 0; i < 8; i++)
            #pragma unroll
            for (int j = 0; j < 8; j++) acc[i][j] += a[i] * b[j];
    }

    float bv[8];
    *(float4*)(bv)     = *(const float4*)&bias[n0];
    *(float4*)(bv + 4) = *(const float4*)&bias[n0 + 4];
    #pragma unroll
    for (int i = 0; i < 8; i++) {
        int gr = row0 + m0 + i;
        if (gr < NN) {
            float o[8];
            #pragma unroll
            for (int j = 0; j < 8; j++) o[j] = acc[i][j] + bv[j];
            if (RESID) {
                float4 r0 = ((const float4*)resid)[gr * 32 + (n0 >> 2)];
                float4 r1 = ((const float4*)resid)[gr * 32 + (n0 >> 2) + 1];
                o[0] += r0.x; o[1] += r0.y; o[2] += r0.z; o[3] += r0.w;
                o[4] += r1.x; o[5] += r1.y; o[6] += r1.z; o[7] += r1.w;
            }
            ((float4*)Out)[gr * 32 + (n0 >> 2)]     = *(float4*)(o);
            ((float4*)Out)[gr * 32 + (n0 >> 2) + 1] = *(float4*)(o + 4);
        }
    }
}

__global__ void __launch_bounds__(256, 1) gemm_qkvs_k(
    const float* __restrict__ Wq, const float* __restrict__ bq,
    const float* __restrict__ Wk, const float* __restrict__ bk,
    const float* __restrict__ Wv, const float* __restrict__ bv,
    const float* __restrict__ Ws, const float* __restrict__ bs) {
    const float* W; const float* b; float* O;
    switch (blockIdx.y) {
        case 0: W = Wq; b = bq; O = g_q; break;
        case 1: W = Wk; b = bk; O = g_k; break;
        case 2: W = Wv; b = bv; O = g_v; break;
        default: W = Ws; b = bs; O = g_sk; break;
    }
    gemm_body<false>(g_h, W, b, O, nullptr);
}

__global__ void __launch_bounds__(256, 1) gemm_final_k(
    const float* __restrict__ Wfc, const float* __restrict__ bfc,
    const float* __restrict__ x, float* __restrict__ out) {
    gemm_body<true>(g_sk, Wfc, bfc, out, x);
}

// ---------------- attention: warp-per-node online softmax over CSR edges ----------------
#define ONLINE(mh, lh, ah, tt, vv)                       \
    if ((tt) > (mh)) {                                   \
        float sc_ = __expf((mh) - (tt));                 \
        (mh) = (tt);                                     \
        (lh) = (lh) * sc_ + 1.f;                         \
        (ah) = (ah) * sc_ + (vv);                        \
    } else {                                             \
        float p_ = __expf((tt) - (mh));                  \
        (lh) += p_;                                      \
        (ah) += p_ * (vv);                               \
    }

__global__ void attn_k() {
    int w = (blockIdx.x * blockDim.x + threadIdx.x) >> 5;
    int lane = threadIdx.x & 31;
    if (w >= NN) return;
    const float inv = 0.17677669529663689f; // 1/sqrt(32)
    int base = w * CH;
    float q0 = g_q[base + lane] * inv;
    float q1 = g_q[base + 32 + lane] * inv;
    float q2 = g_q[base + 64 + lane] * inv;
    float q3 = g_q[base + 96 + lane] * inv;
    int beg = g_rowptr[w], end = g_rowptr[w + 1];

    float m0 = -1e30f, m1 = -1e30f, m2 = -1e30f, m3 = -1e30f;
    float l0 = 0.f, l1 = 0.f, l2 = 0.f, l3 = 0.f;
    float a0 = 0.f, a1 = 0.f, a2 = 0.f, a3 = 0.f;

    for (int e = beg; e < end; e++) {
        int s = g_esrc[e];
        const float* kp = g_k + s * CH;
        const float* vp = g_v + s * CH;
        float k0 = __ldg(kp + lane), k1 = __ldg(kp + 32 + lane);
        float k2 = __ldg(kp + 64 + lane), k3 = __ldg(kp + 96 + lane);
        float v0 = __ldg(vp + lane), v1 = __ldg(vp + 32 + lane);
        float v2 = __ldg(vp + 64 + lane), v3 = __ldg(vp + 96 + lane);
        float t0 = q0 * k0, t1 = q1 * k1, t2 = q2 * k2, t3 = q3 * k3;
        #pragma unroll
        for (int o = 16; o; o >>= 1) {
            t0 += __shfl_xor_sync(0xffffffffu, t0, o);
            t1 += __shfl_xor_sync(0xffffffffu, t1, o);
            t2 += __shfl_xor_sync(0xffffffffu, t2, o);
            t3 += __shfl_xor_sync(0xffffffffu, t3, o);
        }
        ONLINE(m0, l0, a0, t0, v0);
        ONLINE(m1, l1, a1, t1, v1);
        ONLINE(m2, l2, a2, t2, v2);
        ONLINE(m3, l3, a3, t3, v3);
    }
    float r0 = (l0 > 0.f) ? a0 / l0 : 0.f;
    float r1 = (l1 > 0.f) ? a1 / l1 : 0.f;
    float r2 = (l2 > 0.f) ? a2 / l2 : 0.f;
    float r3 = (l3 > 0.f) ? a3 / l3 : 0.f;
    // conv = agg + skip (in place)
    g_sk[base + lane]      += r0;
    g_sk[base + 32 + lane] += r1;
    g_sk[base + 64 + lane] += r2;
    g_sk[base + 96 + lane] += r3;
}

// ---------------- launch ----------------
extern "C" void kernel_launch(void* const* d_in, const int* in_sizes, int n_in,
                              void* d_out, int out_size) {
    const float* x         = (const float*)d_in[0];
    const void* ei         = d_in[1];
    const float* bn_gamma  = (const float*)d_in[2];
    const float* bn_beta   = (const float*)d_in[3];
    const float* Wq        = (const float*)d_in[4];
    const float* bq        = (const float*)d_in[5];
    const float* Wk        = (const float*)d_in[6];
    const float* bk        = (const float*)d_in[7];
    const float* Wv        = (const float*)d_in[8];
    const float* bv        = (const float*)d_in[9];
    const float* Wskip     = (const float*)d_in[10];
    const float* bskip     = (const float*)d_in[11];
    const float* Wfc       = (const float*)d_in[12];
    const float* bfc       = (const float*)d_in[13];
    float* out = (float*)d_out;

    const int SMEM = (128 * 132 + 128 * 128) * 4;
    cudaFuncSetAttribute(gemm_qkvs_k, cudaFuncAttributeMaxDynamicSharedMemorySize, SMEM);
    cudaFuncSetAttribute(gemm_final_k, cudaFuncAttributeMaxDynamicSharedMemorySize, SMEM);

    const int MBLK = (NN + 127) / 128; // 782

    detect_k<<<1, 32>>>((const long long*)ei);
    init_k<<<256, 256>>>();
    bn_stats_k<<<512, 128>>>(x);
    bn_finalize_k<<<1, 128>>>(bn_gamma, bn_beta);
    bn_apply_k<<<(NN * CH / 4 + 255) / 256, 256>>>(x);
    hist_k<<<(NE + 255) / 256, 256>>>(ei);
    scan_k<<<1, 1024>>>();
    scatter_k<<<(NE + 255) / 256, 256>>>(ei);
    gemm_qkvs_k<<<dim3(MBLK, 4), 256, SMEM>>>(Wq, bq, Wk, bk, Wv, bv, Wskip, bskip);
    attn_k<<<(NN * 32 + 255) / 256, 256>>>();
    gemm_final_k<<<MBLK, 256, SMEM>>>(Wfc, bfc, x, out);
}

// round 3
// speedup vs baseline: 1.3108x; 1.3108x over previous
#include <cuda_runtime.h>
#include <math.h>
#include <stdint.h>

#define NN 100000
#define NE 1600000
#define CH 128          // channels = H*D
#define NH 4
#define HD 32
#define EPS 1e-5f

// ---------------- scratch (device globals; no allocation allowed) ----------------
__device__ __align__(128) float g_h[NN * CH];
__device__ __align__(128) float g_q[NN * CH];
__device__ __align__(128) float g_k[NN * CH];
__device__ __align__(128) float g_v[NN * CH];
__device__ __align__(128) float g_sk[NN * CH];   // skip, then conv (in-place)
__device__ __align__(128) float g_stats[4 * CH]; // sum, sumsq, scale, shift
__device__ int g_cnt[NN];
__device__ int g_rowptr[NN + 1];
__device__ int g_cursor[NN];
__device__ int g_esrc[NE];
__device__ int g_is64;

// ---------------- edge dtype detection ----------------
__global__ void detect_k(const long long* __restrict__ ei) {
    if (threadIdx.x == 0) {
        int ok = 1;
        for (int i = 0; i < 256; i++) {
            long long v = ei[i];
            if (v < 0 || v >= NN) { ok = 0; break; }
        }
        g_is64 = ok;
    }
}

__device__ __forceinline__ int edge_at(const void* ei, int idx) {
    return g_is64 ? (int)((const long long*)ei)[idx] : ((const int*)ei)[idx];
}

// ---------------- init ----------------
__global__ void init_k() {
    int i = blockIdx.x * blockDim.x + threadIdx.x;
    if (i < 2 * CH) g_stats[i] = 0.f;
    for (int j = i; j < NN; j += gridDim.x * blockDim.x) g_cnt[j] = 0;
}

// ---------------- batchnorm stats ----------------
__global__ void bn_stats_k(const float* __restrict__ x) {
    int c = threadIdx.x; // 128 threads
    float s = 0.f, sq = 0.f;
    for (int r = blockIdx.x; r < NN; r += gridDim.x) {
        float v = x[r * CH + c];
        s += v; sq += v * v;
    }
    atomicAdd(&g_stats[c], s);
    atomicAdd(&g_stats[CH + c], sq);
}

__global__ void bn_finalize_k(const float* __restrict__ gamma, const float* __restrict__ beta) {
    int c = threadIdx.x;
    float mean = g_stats[c] / (float)NN;
    float var = g_stats[CH + c] / (float)NN - mean * mean;
    float scale = gamma[c] * rsqrtf(var + EPS);
    g_stats[2 * CH + c] = scale;
    g_stats[3 * CH + c] = beta[c] - mean * scale;
}

// ---------------- h = relu(bn(x)) ----------------
__global__ void bn_apply_k(const float* __restrict__ x) {
    int i = blockIdx.x * blockDim.x + threadIdx.x; // float4 index
    if (i < NN * CH / 4) {
        float4 xv = ((const float4*)x)[i];
        int c4 = i & 31;
        float4 sc = ((const float4*)(g_stats + 2 * CH))[c4];
        float4 sh = ((const float4*)(g_stats + 3 * CH))[c4];
        float4 h;
        h.x = fmaxf(0.f, xv.x * sc.x + sh.x);
        h.y = fmaxf(0.f, xv.y * sc.y + sh.y);
        h.z = fmaxf(0.f, xv.z * sc.z + sh.z);
        h.w = fmaxf(0.f, xv.w * sc.w + sh.w);
        ((float4*)g_h)[i] = h;
    }
}

// ---------------- CSR build ----------------
__global__ void hist_k(const void* __restrict__ ei) {
    int e = blockIdx.x * blockDim.x + threadIdx.x;
    if (e < NE) {
        int d = edge_at(ei, NE + e);
        if (d >= 0 && d < NN) atomicAdd(&g_cnt[d], 1);
    }
}

__global__ void scan_k() {
    __shared__ int warpsum[32];
    __shared__ int s_carry;
    int t = threadIdx.x, lane = t & 31, wid = t >> 5;
    if (t == 0) s_carry = 0;
    __syncthreads();
    for (int base = 0; base < NN; base += 1024) {
        int v = (base + t < NN) ? g_cnt[base + t] : 0;
        int x = v;
        #pragma unroll
        for (int o = 1; o < 32; o <<= 1) {
            int y = __shfl_up_sync(0xffffffffu, x, o);
            if (lane >= o) x += y;
        }
        if (lane == 31) warpsum[wid] = x;
        __syncthreads();
        if (wid == 0) {
            int w = warpsum[lane];
            #pragma unroll
            for (int o = 1; o < 32; o <<= 1) {
                int y = __shfl_up_sync(0xffffffffu, w, o);
                if (lane >= o) w += y;
            }
            warpsum[lane] = w;
        }
        __syncthreads();
        int carry = s_carry;
        int prefix = (wid > 0) ? warpsum[wid - 1] : 0;
        int incl = x + prefix;
        int excl = incl - v + carry;
        if (base + t < NN) { g_rowptr[base + t] = excl; g_cursor[base + t] = excl; }
        __syncthreads();
        if (t == 1023) s_carry = carry + incl;
        __syncthreads();
    }
    if (t == 0) g_rowptr[NN] = s_carry;
}

__global__ void scatter_k(const void* __restrict__ ei) {
    int e = blockIdx.x * blockDim.x + threadIdx.x;
    if (e < NE) {
        int d = edge_at(ei, NE + e);
        int s = edge_at(ei, e);
        if (d >= 0 && d < NN && s >= 0 && s < NN) {
            int pos = atomicAdd(&g_cursor[d], 1);
            if (pos >= 0 && pos < NE) g_esrc[pos] = s;
        }
    }
}

// ---------------- tf32 tensor-core GEMM: Out[M,128] = A[M,128] @ W[128,128] + bias (+resid) ----
#define LDA 132   // As row stride: bank = 4g+t -> conflict-free A frag loads
#define LDW 136   // Ws row stride: bank = 8t+g -> conflict-free B frag loads

__device__ __forceinline__ float tf32r(float x) {
    uint32_t u;
    asm("cvt.rna.tf32.f32 %0, %1;" : "=r"(u) : "f"(x));
    return __uint_as_float(u);
}

__device__ __forceinline__ void mma_tf32(float* c, const uint32_t* a, uint32_t b0, uint32_t b1) {
    asm volatile(
        "mma.sync.aligned.m16n8k8.row.col.f32.tf32.tf32.f32 "
        "{%0,%1,%2,%3}, {%4,%5,%6,%7}, {%8,%9}, {%0,%1,%2,%3};"
        : "+f"(c[0]), "+f"(c[1]), "+f"(c[2]), "+f"(c[3])
        : "r"(a[0]), "r"(a[1]), "r"(a[2]), "r"(a[3]), "r"(b0), "r"(b1));
}

template <bool RESID>
__device__ __forceinline__ void gemm_mma_body(const float* __restrict__ A, const float* __restrict__ W,
                                              const float* __restrict__ bias, float* __restrict__ Out,
                                              const float* __restrict__ resid) {
    extern __shared__ float sm[];
    float* As = sm;              // [128][LDA]
    float* Ws = sm + 128 * LDA;  // [128][LDW]
    const int t = threadIdx.x;
    const int row0 = blockIdx.x * 128;

    // stage A and W (tf32-rounded) into smem
    #pragma unroll
    for (int i = 0; i < 16; i++) {
        int lin = i * 256 + t;          // float4 index into 128x128 tile
        int r = lin >> 5, c4 = lin & 31;
        int gr = row0 + r;
        float4 a = (gr < NN) ? ((const float4*)A)[gr * 32 + c4] : make_float4(0.f, 0.f, 0.f, 0.f);
        a.x = tf32r(a.x); a.y = tf32r(a.y); a.z = tf32r(a.z); a.w = tf32r(a.w);
        *(float4*)&As[r * LDA + c4 * 4] = a;
        float4 w = ((const float4*)W)[lin];
        w.x = tf32r(w.x); w.y = tf32r(w.y); w.z = tf32r(w.z); w.w = tf32r(w.w);
        *(float4*)&Ws[r * LDW + c4 * 4] = w;
    }
    __syncthreads();

    const int lane = t & 31, wrp = t >> 5;
    const int wm = wrp & 3, wn = wrp >> 2;   // warp tile: rows wm*32..+31, cols wn*64..+63
    const int g = lane >> 2, tg = lane & 3;

    float acc[2][8][4];
    #pragma unroll
    for (int mi = 0; mi < 2; mi++)
        #pragma unroll
        for (int nj = 0; nj < 8; nj++)
            #pragma unroll
            for (int c = 0; c < 4; c++) acc[mi][nj][c] = 0.f;

    #pragma unroll
    for (int ks = 0; ks < 16; ks++) {
        const int k0 = ks * 8;
        uint32_t a[2][4];
        #pragma unroll
        for (int mi = 0; mi < 2; mi++) {
            const float* p = As + (wm * 32 + mi * 16 + g) * LDA + k0 + tg;
            a[mi][0] = __float_as_uint(p[0]);
            a[mi][1] = __float_as_uint(p[8 * LDA]);
            a[mi][2] = __float_as_uint(p[4]);
            a[mi][3] = __float_as_uint(p[8 * LDA + 4]);
        }
        #pragma unroll
        for (int nj = 0; nj < 8; nj++) {
            const float* qp = Ws + (k0 + tg) * LDW + wn * 64 + nj * 8 + g;
            uint32_t b0 = __float_as_uint(qp[0]);
            uint32_t b1 = __float_as_uint(qp[4 * LDW]);
            mma_tf32(acc[0][nj], a[0], b0, b1);
            mma_tf32(acc[1][nj], a[1], b0, b1);
        }
    }

    // epilogue: bias (+resid) and store
    #pragma unroll
    for (int mi = 0; mi < 2; mi++) {
        #pragma unroll
        for (int half = 0; half < 2; half++) {
            int gr = row0 + wm * 32 + mi * 16 + g + half * 8;
            if (gr < NN) {
                #pragma unroll
                for (int nj = 0; nj < 8; nj++) {
                    int col = wn * 64 + nj * 8 + 2 * tg;
                    float c0 = acc[mi][nj][half * 2 + 0] + __ldg(&bias[col]);
                    float c1 = acc[mi][nj][half * 2 + 1] + __ldg(&bias[col + 1]);
                    if (RESID) {
                        float2 rr = *(const float2*)&resid[gr * 128 + col];
                        c0 += rr.x; c1 += rr.y;
                    }
                    *(float2*)&Out[gr * 128 + col] = make_float2(c0, c1);
                }
            }
        }
    }
}

__global__ void __launch_bounds__(256, 1) gemm_qkvs_k(
    const float* __restrict__ Wq, const float* __restrict__ bq,
    const float* __restrict__ Wk, const float* __restrict__ bk,
    const float* __restrict__ Wv, const float* __restrict__ bv,
    const float* __restrict__ Ws, const float* __restrict__ bs) {
    const float* W; const float* b; float* O;
    switch (blockIdx.y) {
        case 0: W = Wq; b = bq; O = g_q; break;
        case 1: W = Wk; b = bk; O = g_k; break;
        case 2: W = Wv; b = bv; O = g_v; break;
        default: W = Ws; b = bs; O = g_sk; break;
    }
    gemm_mma_body<false>(g_h, W, b, O, nullptr);
}

__global__ void __launch_bounds__(256, 1) gemm_final_k(
    const float* __restrict__ Wfc, const float* __restrict__ bfc,
    const float* __restrict__ x, float* __restrict__ out) {
    gemm_mma_body<true>(g_sk, Wfc, bfc, out, x);
}

// ---------------- attention: warp-per-node online softmax over CSR edges ----------------
#define ONLINE(mh, lh, ah, tt, vv)                       \
    if ((tt) > (mh)) {                                   \
        float sc_ = __expf((mh) - (tt));                 \
        (mh) = (tt);                                     \
        (lh) = (lh) * sc_ + 1.f;                         \
        (ah) = (ah) * sc_ + (vv);                        \
    } else {                                             \
        float p_ = __expf((tt) - (mh));                  \
        (lh) += p_;                                      \
        (ah) += p_ * (vv);                               \
    }

__global__ void attn_k() {
    int w = (blockIdx.x * blockDim.x + threadIdx.x) >> 5;
    int lane = threadIdx.x & 31;
    if (w >= NN) return;
    const float inv = 0.17677669529663689f; // 1/sqrt(32)
    int base = w * CH;
    float q0 = g_q[base + lane] * inv;
    float q1 = g_q[base + 32 + lane] * inv;
    float q2 = g_q[base + 64 + lane] * inv;
    float q3 = g_q[base + 96 + lane] * inv;
    int beg = g_rowptr[w], end = g_rowptr[w + 1];

    float m0 = -1e30f, m1 = -1e30f, m2 = -1e30f, m3 = -1e30f;
    float l0 = 0.f, l1 = 0.f, l2 = 0.f, l3 = 0.f;
    float a0 = 0.f, a1 = 0.f, a2 = 0.f, a3 = 0.f;

    for (int e = beg; e < end; e++) {
        int s = g_esrc[e];
        const float* kp = g_k + s * CH;
        const float* vp = g_v + s * CH;
        float k0 = __ldg(kp + lane), k1 = __ldg(kp + 32 + lane);
        float k2 = __ldg(kp + 64 + lane), k3 = __ldg(kp + 96 + lane);
        float v0 = __ldg(vp + lane), v1 = __ldg(vp + 32 + lane);
        float v2 = __ldg(vp + 64 + lane), v3 = __ldg(vp + 96 + lane);
        float t0 = q0 * k0, t1 = q1 * k1, t2 = q2 * k2, t3 = q3 * k3;
        #pragma unroll
        for (int o = 16; o; o >>= 1) {
            t0 += __shfl_xor_sync(0xffffffffu, t0, o);
            t1 += __shfl_xor_sync(0xffffffffu, t1, o);
            t2 += __shfl_xor_sync(0xffffffffu, t2, o);
            t3 += __shfl_xor_sync(0xffffffffu, t3, o);
        }
        ONLINE(m0, l0, a0, t0, v0);
        ONLINE(m1, l1, a1, t1, v1);
        ONLINE(m2, l2, a2, t2, v2);
        ONLINE(m3, l3, a3, t3, v3);
    }
    float r0 = (l0 > 0.f) ? a0 / l0 : 0.f;
    float r1 = (l1 > 0.f) ? a1 / l1 : 0.f;
    float r2 = (l2 > 0.f) ? a2 / l2 : 0.f;
    float r3 = (l3 > 0.f) ? a3 / l3 : 0.f;
    // conv = agg + skip (in place)
    g_sk[base + lane]      += r0;
    g_sk[base + 32 + lane] += r1;
    g_sk[base + 64 + lane] += r2;
    g_sk[base + 96 + lane] += r3;
}

// ---------------- launch ----------------
extern "C" void kernel_launch(void* const* d_in, const int* in_sizes, int n_in,
                              void* d_out, int out_size) {
    const float* x         = (const float*)d_in[0];
    const void* ei         = d_in[1];
    const float* bn_gamma  = (const float*)d_in[2];
    const float* bn_beta   = (const float*)d_in[3];
    const float* Wq        = (const float*)d_in[4];
    const float* bq        = (const float*)d_in[5];
    const float* Wk        = (const float*)d_in[6];
    const float* bk        = (const float*)d_in[7];
    const float* Wv        = (const float*)d_in[8];
    const float* bv        = (const float*)d_in[9];
    const float* Wskip     = (const float*)d_in[10];
    const float* bskip     = (const float*)d_in[11];
    const float* Wfc       = (const float*)d_in[12];
    const float* bfc       = (const float*)d_in[13];
    float* out = (float*)d_out;

    const int SMEM = (128 * LDA + 128 * LDW) * 4;  // 137216 B
    cudaFuncSetAttribute(gemm_qkvs_k, cudaFuncAttributeMaxDynamicSharedMemorySize, SMEM);
    cudaFuncSetAttribute(gemm_final_k, cudaFuncAttributeMaxDynamicSharedMemorySize, SMEM);

    const int MBLK = (NN + 127) / 128; // 782

    detect_k<<<1, 32>>>((const long long*)ei);
    init_k<<<256, 256>>>();
    bn_stats_k<<<512, 128>>>(x);
    bn_finalize_k<<<1, 128>>>(bn_gamma, bn_beta);
    bn_apply_k<<<(NN * CH / 4 + 255) / 256, 256>>>(x);
    hist_k<<<(NE + 255) / 256, 256>>>(ei);
    scan_k<<<1, 1024>>>();
    scatter_k<<<(NE + 255) / 256, 256>>>(ei);
    gemm_qkvs_k<<<dim3(MBLK, 4), 256, SMEM>>>(Wq, bq, Wk, bk, Wv, bv, Wskip, bskip);
    attn_k<<<(NN * 32 + 255) / 256, 256>>>();
    gemm_final_k<<<MBLK, 256, SMEM>>>(Wfc, bfc, x, out);
}

// round 4
// speedup vs baseline: 1.6300x; 1.2435x over previous
#include <cuda_runtime.h>
#include <math.h>
#include <stdint.h>

#define NN 100000
#define NE 1600000
#define CH 128          // channels = H*D
#define NH 4
#define HD 32
#define EPS 1e-5f

// ---------------- scratch (device globals; no allocation allowed) ----------------
__device__ __align__(128) float g_q[NN * CH];
__device__ __align__(128) float g_k[NN * CH];
__device__ __align__(128) float g_v[NN * CH];
__device__ __align__(128) float g_sk[NN * CH];   // skip, then conv (in-place)
__device__ __align__(128) float g_stats[4 * CH]; // sum, sumsq, scale, shift
__device__ int g_cnt[NN];
__device__ int g_rowptr[NN + 1];
__device__ int g_cursor[NN];
__device__ int g_esrc[NE];
__device__ int g_is64;

// ---------------- edge dtype detection ----------------
__global__ void detect_k(const long long* __restrict__ ei) {
    if (threadIdx.x == 0) {
        int ok = 1;
        for (int i = 0; i < 256; i++) {
            long long v = ei[i];
            if (v < 0 || v >= NN) { ok = 0; break; }
        }
        g_is64 = ok;
    }
}

__device__ __forceinline__ int edge_at(const void* ei, int idx) {
    return g_is64 ? (int)((const long long*)ei)[idx] : ((const int*)ei)[idx];
}

// ---------------- init ----------------
__global__ void init_k() {
    int i = blockIdx.x * blockDim.x + threadIdx.x;
    if (i < 2 * CH) g_stats[i] = 0.f;
    for (int j = i; j < NN; j += gridDim.x * blockDim.x) g_cnt[j] = 0;
}

// ---------------- batchnorm stats ----------------
__global__ void bn_stats_k(const float* __restrict__ x) {
    int c = threadIdx.x; // 128 threads
    float s = 0.f, sq = 0.f;
    for (int r = blockIdx.x; r < NN; r += gridDim.x) {
        float v = x[r * CH + c];
        s += v; sq += v * v;
    }
    atomicAdd(&g_stats[c], s);
    atomicAdd(&g_stats[CH + c], sq);
}

__global__ void bn_finalize_k(const float* __restrict__ gamma, const float* __restrict__ beta) {
    int c = threadIdx.x;
    float mean = g_stats[c] / (float)NN;
    float var = g_stats[CH + c] / (float)NN - mean * mean;
    float scale = gamma[c] * rsqrtf(var + EPS);
    g_stats[2 * CH + c] = scale;
    g_stats[3 * CH + c] = beta[c] - mean * scale;
}

// ---------------- CSR build ----------------
__global__ void hist_k(const void* __restrict__ ei) {
    int e = blockIdx.x * blockDim.x + threadIdx.x;
    if (e < NE) {
        int d = edge_at(ei, NE + e);
        if (d >= 0 && d < NN) atomicAdd(&g_cnt[d], 1);
    }
}

__global__ void scan_k() {
    __shared__ int warpsum[32];
    __shared__ int s_carry;
    int t = threadIdx.x, lane = t & 31, wid = t >> 5;
    if (t == 0) s_carry = 0;
    __syncthreads();
    for (int base = 0; base < NN; base += 1024) {
        int v = (base + t < NN) ? g_cnt[base + t] : 0;
        int x = v;
        #pragma unroll
        for (int o = 1; o < 32; o <<= 1) {
            int y = __shfl_up_sync(0xffffffffu, x, o);
            if (lane >= o) x += y;
        }
        if (lane == 31) warpsum[wid] = x;
        __syncthreads();
        if (wid == 0) {
            int w = warpsum[lane];
            #pragma unroll
            for (int o = 1; o < 32; o <<= 1) {
                int y = __shfl_up_sync(0xffffffffu, w, o);
                if (lane >= o) w += y;
            }
            warpsum[lane] = w;
        }
        __syncthreads();
        int carry = s_carry;
        int prefix = (wid > 0) ? warpsum[wid - 1] : 0;
        int incl = x + prefix;
        int excl = incl - v + carry;
        if (base + t < NN) { g_rowptr[base + t] = excl; g_cursor[base + t] = excl; }
        __syncthreads();
        if (t == 1023) s_carry = carry + incl;
        __syncthreads();
    }
    if (t == 0) g_rowptr[NN] = s_carry;
}

__global__ void scatter_k(const void* __restrict__ ei) {
    int e = blockIdx.x * blockDim.x + threadIdx.x;
    if (e < NE) {
        int d = edge_at(ei, NE + e);
        int s = edge_at(ei, e);
        if (d >= 0 && d < NN && s >= 0 && s < NN) {
            int pos = atomicAdd(&g_cursor[d], 1);
            if (pos >= 0 && pos < NE) g_esrc[pos] = s;
        }
    }
}

// ---------------- tf32 tensor-core GEMM: Out[M,128] = A[M,128] @ W[128,128] + bias (+resid) ----
// APPLY_BN: A is raw x, apply scale/shift+relu during staging (fused BatchNorm+ReLU).
#define LDA 132   // As row stride: bank = 4g+t -> conflict-free A frag loads
#define LDW 136   // Ws row stride: bank = 8t+g -> conflict-free B frag loads

__device__ __forceinline__ float tf32r(float x) {
    uint32_t u;
    asm("cvt.rna.tf32.f32 %0, %1;" : "=r"(u) : "f"(x));
    return __uint_as_float(u);
}

__device__ __forceinline__ void mma_tf32(float* c, const uint32_t* a, uint32_t b0, uint32_t b1) {
    asm volatile(
        "mma.sync.aligned.m16n8k8.row.col.f32.tf32.tf32.f32 "
        "{%0,%1,%2,%3}, {%4,%5,%6,%7}, {%8,%9}, {%0,%1,%2,%3};"
        : "+f"(c[0]), "+f"(c[1]), "+f"(c[2]), "+f"(c[3])
        : "r"(a[0]), "r"(a[1]), "r"(a[2]), "r"(a[3]), "r"(b0), "r"(b1));
}

template <bool RESID, bool APPLY_BN>
__device__ __forceinline__ void gemm_mma_body(const float* __restrict__ A, const float* __restrict__ W,
                                              const float* __restrict__ bias, float* __restrict__ Out,
                                              const float* __restrict__ resid) {
    extern __shared__ float sm[];
    float* As = sm;              // [128][LDA]
    float* Ws = sm + 128 * LDA;  // [128][LDW]
    const int t = threadIdx.x;
    const int row0 = blockIdx.x * 128;

    // stage A and W (tf32-rounded) into smem
    #pragma unroll
    for (int i = 0; i < 16; i++) {
        int lin = i * 256 + t;          // float4 index into 128x128 tile
        int r = lin >> 5, c4 = lin & 31;
        int gr = row0 + r;
        float4 a = (gr < NN) ? ((const float4*)A)[gr * 32 + c4] : make_float4(0.f, 0.f, 0.f, 0.f);
        if (APPLY_BN) {
            float4 sc = ((const float4*)(g_stats + 2 * CH))[c4];
            float4 sh = ((const float4*)(g_stats + 3 * CH))[c4];
            a.x = fmaxf(0.f, a.x * sc.x + sh.x);
            a.y = fmaxf(0.f, a.y * sc.y + sh.y);
            a.z = fmaxf(0.f, a.z * sc.z + sh.z);
            a.w = fmaxf(0.f, a.w * sc.w + sh.w);
        }
        a.x = tf32r(a.x); a.y = tf32r(a.y); a.z = tf32r(a.z); a.w = tf32r(a.w);
        *(float4*)&As[r * LDA + c4 * 4] = a;
        float4 w = ((const float4*)W)[lin];
        w.x = tf32r(w.x); w.y = tf32r(w.y); w.z = tf32r(w.z); w.w = tf32r(w.w);
        *(float4*)&Ws[r * LDW + c4 * 4] = w;
    }
    __syncthreads();

    const int lane = t & 31, wrp = t >> 5;
    const int wm = wrp & 3, wn = wrp >> 2;   // warp tile: rows wm*32..+31, cols wn*64..+63
    const int g = lane >> 2, tg = lane & 3;

    float acc[2][8][4];
    #pragma unroll
    for (int mi = 0; mi < 2; mi++)
        #pragma unroll
        for (int nj = 0; nj < 8; nj++)
            #pragma unroll
            for (int c = 0; c < 4; c++) acc[mi][nj][c] = 0.f;

    #pragma unroll
    for (int ks = 0; ks < 16; ks++) {
        const int k0 = ks * 8;
        uint32_t a[2][4];
        #pragma unroll
        for (int mi = 0; mi < 2; mi++) {
            const float* p = As + (wm * 32 + mi * 16 + g) * LDA + k0 + tg;
            a[mi][0] = __float_as_uint(p[0]);
            a[mi][1] = __float_as_uint(p[8 * LDA]);
            a[mi][2] = __float_as_uint(p[4]);
            a[mi][3] = __float_as_uint(p[8 * LDA + 4]);
        }
        #pragma unroll
        for (int nj = 0; nj < 8; nj++) {
            const float* qp = Ws + (k0 + tg) * LDW + wn * 64 + nj * 8 + g;
            uint32_t b0 = __float_as_uint(qp[0]);
            uint32_t b1 = __float_as_uint(qp[4 * LDW]);
            mma_tf32(acc[0][nj], a[0], b0, b1);
            mma_tf32(acc[1][nj], a[1], b0, b1);
        }
    }

    // epilogue: bias (+resid) and store
    #pragma unroll
    for (int mi = 0; mi < 2; mi++) {
        #pragma unroll
        for (int half = 0; half < 2; half++) {
            int gr = row0 + wm * 32 + mi * 16 + g + half * 8;
            if (gr < NN) {
                #pragma unroll
                for (int nj = 0; nj < 8; nj++) {
                    int col = wn * 64 + nj * 8 + 2 * tg;
                    float c0 = acc[mi][nj][half * 2 + 0] + __ldg(&bias[col]);
                    float c1 = acc[mi][nj][half * 2 + 1] + __ldg(&bias[col + 1]);
                    if (RESID) {
                        float2 rr = *(const float2*)&resid[gr * 128 + col];
                        c0 += rr.x; c1 += rr.y;
                    }
                    *(float2*)&Out[gr * 128 + col] = make_float2(c0, c1);
                }
            }
        }
    }
}

__global__ void __launch_bounds__(256, 1) gemm_qkvs_k(
    const float* __restrict__ x,
    const float* __restrict__ Wq, const float* __restrict__ bq,
    const float* __restrict__ Wk, const float* __restrict__ bk,
    const float* __restrict__ Wv, const float* __restrict__ bv,
    const float* __restrict__ Ws, const float* __restrict__ bs) {
    const float* W; const float* b; float* O;
    switch (blockIdx.y) {
        case 0: W = Wq; b = bq; O = g_q; break;
        case 1: W = Wk; b = bk; O = g_k; break;
        case 2: W = Wv; b = bv; O = g_v; break;
        default: W = Ws; b = bs; O = g_sk; break;
    }
    gemm_mma_body<false, true>(x, W, b, O, nullptr);
}

__global__ void __launch_bounds__(256, 1) gemm_final_k(
    const float* __restrict__ Wfc, const float* __restrict__ bfc,
    const float* __restrict__ x, float* __restrict__ out) {
    gemm_mma_body<true, false>(g_sk, Wfc, bfc, out, x);
}

// ---------------- attention: warp-per-node, lane = float4 chunk (head = lane>>3) ----------------
__global__ void attn_k() {
    int w = (blockIdx.x * blockDim.x + threadIdx.x) >> 5;
    int lane = threadIdx.x & 31;
    if (w >= NN) return;
    const float inv = 0.17677669529663689f; // 1/sqrt(32)
    const int off = lane * 4;               // floats [4l,4l+4); head = lane>>3
    const int base = w * CH;

    float4 q4 = *(const float4*)&g_q[base + off];
    q4.x *= inv; q4.y *= inv; q4.z *= inv; q4.w *= inv;

    int beg = g_rowptr[w], end = g_rowptr[w + 1];
    float m = -1e30f, l = 0.f;
    float4 acc = make_float4(0.f, 0.f, 0.f, 0.f);

    for (int e = beg; e < end; e++) {
        int s = __ldg(&g_esrc[e]);
        float4 k4 = *(const float4*)&g_k[s * CH + off];
        float4 v4 = *(const float4*)&g_v[s * CH + off];
        // per-head dot: reduce within 8-lane segment (4 heads in parallel)
        float tt = q4.x * k4.x + q4.y * k4.y + q4.z * k4.z + q4.w * k4.w;
        tt += __shfl_xor_sync(0xffffffffu, tt, 1);
        tt += __shfl_xor_sync(0xffffffffu, tt, 2);
        tt += __shfl_xor_sync(0xffffffffu, tt, 4);
        // branchless online softmax
        float nm = fmaxf(m, tt);
        float sc = __expf(m - nm);
        float p  = __expf(tt - nm);
        m = nm;
        l = l * sc + p;
        acc.x = acc.x * sc + p * v4.x;
        acc.y = acc.y * sc + p * v4.y;
        acc.z = acc.z * sc + p * v4.z;
        acc.w = acc.w * sc + p * v4.w;
    }
    if (l > 0.f) {
        float r = 1.f / l;
        float4 o = *(float4*)&g_sk[base + off];
        o.x += acc.x * r;
        o.y += acc.y * r;
        o.z += acc.z * r;
        o.w += acc.w * r;
        *(float4*)&g_sk[base + off] = o;
    }
}

// ---------------- launch ----------------
extern "C" void kernel_launch(void* const* d_in, const int* in_sizes, int n_in,
                              void* d_out, int out_size) {
    const float* x         = (const float*)d_in[0];
    const void* ei         = d_in[1];
    const float* bn_gamma  = (const float*)d_in[2];
    const float* bn_beta   = (const float*)d_in[3];
    const float* Wq        = (const float*)d_in[4];
    const float* bq        = (const float*)d_in[5];
    const float* Wk        = (const float*)d_in[6];
    const float* bk        = (const float*)d_in[7];
    const float* Wv        = (const float*)d_in[8];
    const float* bv        = (const float*)d_in[9];
    const float* Wskip     = (const float*)d_in[10];
    const float* bskip     = (const float*)d_in[11];
    const float* Wfc       = (const float*)d_in[12];
    const float* bfc       = (const float*)d_in[13];
    float* out = (float*)d_out;

    const int SMEM = (128 * LDA + 128 * LDW) * 4;  // 137216 B
    cudaFuncSetAttribute(gemm_qkvs_k, cudaFuncAttributeMaxDynamicSharedMemorySize, SMEM);
    cudaFuncSetAttribute(gemm_final_k, cudaFuncAttributeMaxDynamicSharedMemorySize, SMEM);

    const int MBLK = (NN + 127) / 128; // 782

    detect_k<<<1, 32>>>((const long long*)ei);
    init_k<<<256, 256>>>();
    bn_stats_k<<<512, 128>>>(x);
    bn_finalize_k<<<1, 128>>>(bn_gamma, bn_beta);
    hist_k<<<(NE + 255) / 256, 256>>>(ei);
    scan_k<<<1, 1024>>>();
    scatter_k<<<(NE + 255) / 256, 256>>>(ei);
    gemm_qkvs_k<<<dim3(MBLK, 4), 256, SMEM>>>(x, Wq, bq, Wk, bk, Wv, bv, Wskip, bskip);
    attn_k<<<(NN * 32 + 255) / 256, 256>>>();
    gemm_final_k<<<MBLK, 256, SMEM>>>(Wfc, bfc, x, out);
}

// round 5
// speedup vs baseline: 1.9636x; 1.2047x over previous
#include <cuda_runtime.h>
#include <math.h>
#include <stdint.h>

#define NN 100000
#define NE 1600000
#define CH 128          // channels = H*D
#define NH 4
#define HD 32
#define EPS 1e-5f

// ---------------- scratch (device globals; no allocation allowed) ----------------
__device__ __align__(128) float g_q[NN * CH];
__device__ __align__(128) float g_k[NN * CH];
__device__ __align__(128) float g_v[NN * CH];
__device__ __align__(128) float g_sk[NN * CH];   // skip, then conv (in-place)
__device__ __align__(128) float g_stats[4 * CH]; // sum, sumsq, scale, shift
__device__ int g_cnt[NN];
__device__ int g_rowptr[NN + 1];
__device__ int g_cursor[NN];
__device__ int g_esrc[NE];
__device__ int g_is64;

// ---------------- edge dtype detection ----------------
__global__ void detect_k(const long long* __restrict__ ei) {
    if (threadIdx.x == 0) {
        int ok = 1;
        for (int i = 0; i < 256; i++) {
            long long v = ei[i];
            if (v < 0 || v >= NN) { ok = 0; break; }
        }
        g_is64 = ok;
    }
}

__device__ __forceinline__ int edge_at(const void* ei, int idx) {
    return g_is64 ? (int)((const long long*)ei)[idx] : ((const int*)ei)[idx];
}

// ---------------- init ----------------
__global__ void init_k() {
    int i = blockIdx.x * blockDim.x + threadIdx.x;
    if (i < 2 * CH) g_stats[i] = 0.f;
    for (int j = i; j < NN; j += gridDim.x * blockDim.x) g_cnt[j] = 0;
}

// ---------------- batchnorm stats ----------------
__global__ void bn_stats_k(const float* __restrict__ x) {
    int c = threadIdx.x; // 128 threads
    float s = 0.f, sq = 0.f;
    for (int r = blockIdx.x; r < NN; r += gridDim.x) {
        float v = x[r * CH + c];
        s += v; sq += v * v;
    }
    atomicAdd(&g_stats[c], s);
    atomicAdd(&g_stats[CH + c], sq);
}

__global__ void bn_finalize_k(const float* __restrict__ gamma, const float* __restrict__ beta) {
    int c = threadIdx.x;
    float mean = g_stats[c] / (float)NN;
    float var = g_stats[CH + c] / (float)NN - mean * mean;
    float scale = gamma[c] * rsqrtf(var + EPS);
    g_stats[2 * CH + c] = scale;
    g_stats[3 * CH + c] = beta[c] - mean * scale;
}

// ---------------- CSR build ----------------
__global__ void hist_k(const void* __restrict__ ei) {
    int e = blockIdx.x * blockDim.x + threadIdx.x;
    if (e < NE) {
        int d = edge_at(ei, NE + e);
        if (d >= 0 && d < NN) atomicAdd(&g_cnt[d], 1);
    }
}

__global__ void scan_k() {
    __shared__ int warpsum[32];
    __shared__ int s_carry;
    int t = threadIdx.x, lane = t & 31, wid = t >> 5;
    if (t == 0) s_carry = 0;
    __syncthreads();
    for (int base = 0; base < NN; base += 1024) {
        int v = (base + t < NN) ? g_cnt[base + t] : 0;
        int x = v;
        #pragma unroll
        for (int o = 1; o < 32; o <<= 1) {
            int y = __shfl_up_sync(0xffffffffu, x, o);
            if (lane >= o) x += y;
        }
        if (lane == 31) warpsum[wid] = x;
        __syncthreads();
        if (wid == 0) {
            int w = warpsum[lane];
            #pragma unroll
            for (int o = 1; o < 32; o <<= 1) {
                int y = __shfl_up_sync(0xffffffffu, w, o);
                if (lane >= o) w += y;
            }
            warpsum[lane] = w;
        }
        __syncthreads();
        int carry = s_carry;
        int prefix = (wid > 0) ? warpsum[wid - 1] : 0;
        int incl = x + prefix;
        int excl = incl - v + carry;
        if (base + t < NN) { g_rowptr[base + t] = excl; g_cursor[base + t] = excl; }
        __syncthreads();
        if (t == 1023) s_carry = carry + incl;
        __syncthreads();
    }
    if (t == 0) g_rowptr[NN] = s_carry;
}

__global__ void scatter_k(const void* __restrict__ ei) {
    int e = blockIdx.x * blockDim.x + threadIdx.x;
    if (e < NE) {
        int d = edge_at(ei, NE + e);
        int s = edge_at(ei, e);
        if (d >= 0 && d < NN && s >= 0 && s < NN) {
            int pos = atomicAdd(&g_cursor[d], 1);
            if (pos >= 0 && pos < NE) g_esrc[pos] = s;
        }
    }
}

// ---------------- tf32 tensor-core GEMM ----------------
#define LDA 132   // As row stride: conflict-free A frag loads
#define LDW 136   // Ws row stride: conflict-free B frag loads

__device__ __forceinline__ float tf32r(float x) {
    uint32_t u;
    asm("cvt.rna.tf32.f32 %0, %1;" : "=r"(u) : "f"(x));
    return __uint_as_float(u);
}

__device__ __forceinline__ void mma_tf32(float* c, const uint32_t* a, uint32_t b0, uint32_t b1) {
    asm volatile(
        "mma.sync.aligned.m16n8k8.row.col.f32.tf32.tf32.f32 "
        "{%0,%1,%2,%3}, {%4,%5,%6,%7}, {%8,%9}, {%0,%1,%2,%3};"
        : "+f"(c[0]), "+f"(c[1]), "+f"(c[2]), "+f"(c[3])
        : "r"(a[0]), "r"(a[1]), "r"(a[2]), "r"(a[3]), "r"(b0), "r"(b1));
}

// stage W tile (tf32) into Ws
__device__ __forceinline__ void stage_w(const float* __restrict__ W, float* Ws, int t) {
    #pragma unroll
    for (int i = 0; i < 16; i++) {
        int lin = i * 256 + t;
        int r = lin >> 5, c4 = lin & 31;
        float4 w = ((const float4*)W)[lin];
        w.x = tf32r(w.x); w.y = tf32r(w.y); w.z = tf32r(w.z); w.w = tf32r(w.w);
        *(float4*)&Ws[r * LDW + c4 * 4] = w;
    }
}

// compute 128x128 @ staged tiles, epilogue bias(+resid), store
template <bool RESID>
__device__ __forceinline__ void mma_compute_store(const float* As, const float* Ws,
                                                  const float* __restrict__ bias,
                                                  float* __restrict__ Out,
                                                  const float* __restrict__ resid,
                                                  int row0, int t) {
    const int lane = t & 31, wrp = t >> 5;
    const int wm = wrp & 3, wn = wrp >> 2;
    const int g = lane >> 2, tg = lane & 3;

    float acc[2][8][4];
    #pragma unroll
    for (int mi = 0; mi < 2; mi++)
        #pragma unroll
        for (int nj = 0; nj < 8; nj++)
            #pragma unroll
            for (int c = 0; c < 4; c++) acc[mi][nj][c] = 0.f;

    #pragma unroll
    for (int ks = 0; ks < 16; ks++) {
        const int k0 = ks * 8;
        uint32_t a[2][4];
        #pragma unroll
        for (int mi = 0; mi < 2; mi++) {
            const float* p = As + (wm * 32 + mi * 16 + g) * LDA + k0 + tg;
            a[mi][0] = __float_as_uint(p[0]);
            a[mi][1] = __float_as_uint(p[8 * LDA]);
            a[mi][2] = __float_as_uint(p[4]);
            a[mi][3] = __float_as_uint(p[8 * LDA + 4]);
        }
        #pragma unroll
        for (int nj = 0; nj < 8; nj++) {
            const float* qp = Ws + (k0 + tg) * LDW + wn * 64 + nj * 8 + g;
            uint32_t b0 = __float_as_uint(qp[0]);
            uint32_t b1 = __float_as_uint(qp[4 * LDW]);
            mma_tf32(acc[0][nj], a[0], b0, b1);
            mma_tf32(acc[1][nj], a[1], b0, b1);
        }
    }

    #pragma unroll
    for (int mi = 0; mi < 2; mi++) {
        #pragma unroll
        for (int half = 0; half < 2; half++) {
            int gr = row0 + wm * 32 + mi * 16 + g + half * 8;
            if (gr < NN) {
                #pragma unroll
                for (int nj = 0; nj < 8; nj++) {
                    int col = wn * 64 + nj * 8 + 2 * tg;
                    float c0 = acc[mi][nj][half * 2 + 0] + __ldg(&bias[col]);
                    float c1 = acc[mi][nj][half * 2 + 1] + __ldg(&bias[col + 1]);
                    if (RESID) {
                        float2 rr = *(const float2*)&resid[gr * 128 + col];
                        c0 += rr.x; c1 += rr.y;
                    }
                    *(float2*)&Out[gr * 128 + col] = make_float2(c0, c1);
                }
            }
        }
    }
}

// fused QKVS: stage A (BN+ReLU+tf32) once, loop 4 weight sets
__global__ void __launch_bounds__(256, 1) gemm_qkvs_fused_k(
    const float* __restrict__ x,
    const float* __restrict__ Wq, const float* __restrict__ bq,
    const float* __restrict__ Wk, const float* __restrict__ bk,
    const float* __restrict__ Wv, const float* __restrict__ bv,
    const float* __restrict__ Ws_, const float* __restrict__ bs) {
    extern __shared__ float sm[];
    float* As = sm;
    float* Ws = sm + 128 * LDA;
    const int t = threadIdx.x;
    const int row0 = blockIdx.x * 128;

    // stage A with fused BN+ReLU+tf32
    #pragma unroll
    for (int i = 0; i < 16; i++) {
        int lin = i * 256 + t;
        int r = lin >> 5, c4 = lin & 31;
        int gr = row0 + r;
        float4 a = (gr < NN) ? ((const float4*)x)[gr * 32 + c4] : make_float4(0.f, 0.f, 0.f, 0.f);
        float4 sc = ((const float4*)(g_stats + 2 * CH))[c4];
        float4 sh = ((const float4*)(g_stats + 3 * CH))[c4];
        a.x = tf32r(fmaxf(0.f, a.x * sc.x + sh.x));
        a.y = tf32r(fmaxf(0.f, a.y * sc.y + sh.y));
        a.z = tf32r(fmaxf(0.f, a.z * sc.z + sh.z));
        a.w = tf32r(fmaxf(0.f, a.w * sc.w + sh.w));
        *(float4*)&As[r * LDA + c4 * 4] = a;
    }

    #pragma unroll 1
    for (int wsel = 0; wsel < 4; wsel++) {
        const float* W; const float* b; float* O;
        switch (wsel) {
            case 0: W = Wq;  b = bq; O = g_q; break;
            case 1: W = Wk;  b = bk; O = g_k; break;
            case 2: W = Wv;  b = bv; O = g_v; break;
            default: W = Ws_; b = bs; O = g_sk; break;
        }
        stage_w(W, Ws, t);
        __syncthreads();
        mma_compute_store<false>(As, Ws, b, O, nullptr, row0, t);
        __syncthreads();   // protect Ws before next staging
    }
}

__global__ void __launch_bounds__(256, 1) gemm_final_k(
    const float* __restrict__ Wfc, const float* __restrict__ bfc,
    const float* __restrict__ x, float* __restrict__ out) {
    extern __shared__ float sm[];
    float* As = sm;
    float* Ws = sm + 128 * LDA;
    const int t = threadIdx.x;
    const int row0 = blockIdx.x * 128;
    #pragma unroll
    for (int i = 0; i < 16; i++) {
        int lin = i * 256 + t;
        int r = lin >> 5, c4 = lin & 31;
        int gr = row0 + r;
        float4 a = (gr < NN) ? ((const float4*)g_sk)[gr * 32 + c4] : make_float4(0.f, 0.f, 0.f, 0.f);
        a.x = tf32r(a.x); a.y = tf32r(a.y); a.z = tf32r(a.z); a.w = tf32r(a.w);
        *(float4*)&As[r * LDA + c4 * 4] = a;
    }
    stage_w(Wfc, Ws, t);
    __syncthreads();
    mma_compute_store<true>(As, Ws, bfc, out, x, row0, t);
}

// ---------------- attention: warp-per-node, lane = float4 chunk (head = lane>>3) ----------------
__global__ void attn_k() {
    int w = (blockIdx.x * blockDim.x + threadIdx.x) >> 5;
    int lane = threadIdx.x & 31;
    if (w >= NN) return;
    const float inv = 0.17677669529663689f; // 1/sqrt(32)
    const int off = lane * 4;               // floats [4l,4l+4); head = lane>>3
    const int base = w * CH;

    float4 q4 = *(const float4*)&g_q[base + off];
    q4.x *= inv; q4.y *= inv; q4.z *= inv; q4.w *= inv;

    int beg = g_rowptr[w], end = g_rowptr[w + 1];
    float m = -1e30f, l = 0.f;
    float4 acc = make_float4(0.f, 0.f, 0.f, 0.f);

    for (int e = beg; e < end; e++) {
        int s = __ldg(&g_esrc[e]);
        float4 k4 = *(const float4*)&g_k[s * CH + off];
        float4 v4 = *(const float4*)&g_v[s * CH + off];
        float tt = q4.x * k4.x + q4.y * k4.y + q4.z * k4.z + q4.w * k4.w;
        tt += __shfl_xor_sync(0xffffffffu, tt, 1);
        tt += __shfl_xor_sync(0xffffffffu, tt, 2);
        tt += __shfl_xor_sync(0xffffffffu, tt, 4);
        float nm = fmaxf(m, tt);
        float sc = __expf(m - nm);
        float p  = __expf(tt - nm);
        m = nm;
        l = l * sc + p;
        acc.x = acc.x * sc + p * v4.x;
        acc.y = acc.y * sc + p * v4.y;
        acc.z = acc.z * sc + p * v4.z;
        acc.w = acc.w * sc + p * v4.w;
    }
    if (l > 0.f) {
        float r = 1.f / l;
        float4 o = *(float4*)&g_sk[base + off];
        o.x += acc.x * r;
        o.y += acc.y * r;
        o.z += acc.z * r;
        o.w += acc.w * r;
        *(float4*)&g_sk[base + off] = o;
    }
}

// ---------------- launch (fork-join: CSR chain || BN+GEMM chain) ----------------
extern "C" void kernel_launch(void* const* d_in, const int* in_sizes, int n_in,
                              void* d_out, int out_size) {
    const float* x         = (const float*)d_in[0];
    const void* ei         = d_in[1];
    const float* bn_gamma  = (const float*)d_in[2];
    const float* bn_beta   = (const float*)d_in[3];
    const float* Wq        = (const float*)d_in[4];
    const float* bq        = (const float*)d_in[5];
    const float* Wk        = (const float*)d_in[6];
    const float* bk        = (const float*)d_in[7];
    const float* Wv        = (const float*)d_in[8];
    const float* bv        = (const float*)d_in[9];
    const float* Wskip     = (const float*)d_in[10];
    const float* bskip     = (const float*)d_in[11];
    const float* Wfc       = (const float*)d_in[12];
    const float* bfc       = (const float*)d_in[13];
    float* out = (float*)d_out;

    static cudaStream_t s_side = nullptr;
    static cudaEvent_t ev_fork = nullptr, ev_join = nullptr;
    if (s_side == nullptr) {
        cudaStreamCreateWithFlags(&s_side, cudaStreamNonBlocking);
        cudaEventCreateWithFlags(&ev_fork, cudaEventDisableTiming);
        cudaEventCreateWithFlags(&ev_join, cudaEventDisableTiming);
    }

    const int SMEM = (128 * LDA + 128 * LDW) * 4;  // 137216 B
    cudaFuncSetAttribute(gemm_qkvs_fused_k, cudaFuncAttributeMaxDynamicSharedMemorySize, SMEM);
    cudaFuncSetAttribute(gemm_final_k, cudaFuncAttributeMaxDynamicSharedMemorySize, SMEM);

    const int MBLK = (NN + 127) / 128; // 782

    // common prologue (main stream)
    detect_k<<<1, 32>>>((const long long*)ei);
    init_k<<<256, 256>>>();

    // fork: CSR chain on side stream
    cudaEventRecord(ev_fork, 0);
    cudaStreamWaitEvent(s_side, ev_fork, 0);
    hist_k<<<(NE + 255) / 256, 256, 0, s_side>>>(ei);
    scan_k<<<1, 1024, 0, s_side>>>();
    scatter_k<<<(NE + 255) / 256, 256, 0, s_side>>>(ei);
    cudaEventRecord(ev_join, s_side);

    // main chain: BN + fused QKVS GEMM
    bn_stats_k<<<512, 128>>>(x);
    bn_finalize_k<<<1, 128>>>(bn_gamma, bn_beta);
    gemm_qkvs_fused_k<<<MBLK, 256, SMEM>>>(x, Wq, bq, Wk, bk, Wv, bv, Wskip, bskip);

    // join: attention needs CSR + q/k/v/skip
    cudaStreamWaitEvent(0, ev_join, 0);
    attn_k<<<(NN * 32 + 255) / 256, 256>>>();
    gemm_final_k<<<MBLK, 256, SMEM>>>(Wfc, bfc, x, out);
}

// round 7
// speedup vs baseline: 1.9718x; 1.0041x over previous
#include <cuda_runtime.h>
#include <math.h>
#include <stdint.h>

#define NN 100000
#define NE 1600000
#define CH 128          // channels = H*D
#define NH 4
#define HD 32
#define EPS 1e-5f
#define NB 98           // ceil(NN/1024) scan blocks

// ---------------- scratch (device globals; no allocation allowed) ----------------
__device__ __align__(128) float g_q[NN * CH];
__device__ __align__(128) float g_k[NN * CH];
__device__ __align__(128) float g_v[NN * CH];
__device__ __align__(128) float g_sk[NN * CH];   // skip, then conv (in-place)
__device__ __align__(128) float g_stats[4 * CH]; // sum, sumsq, scale, shift
__device__ int g_cnt[NN];
__device__ int g_rowptr[NN + 1];
__device__ int g_cursor[NN];
__device__ int g_esrc[NE];
__device__ int g_blksum[128];
__device__ int g_blkoff[128];
__device__ int g_is64;

// ---------------- edge dtype detection ----------------
__global__ void detect_k(const long long* __restrict__ ei) {
    if (threadIdx.x == 0) {
        int ok = 1;
        for (int i = 0; i < 256; i++) {
            long long v = ei[i];
            if (v < 0 || v >= NN) { ok = 0; break; }
        }
        g_is64 = ok;
    }
}

__device__ __forceinline__ int edge_at(const void* ei, int idx) {
    return g_is64 ? (int)((const long long*)ei)[idx] : ((const int*)ei)[idx];
}

// ---------------- init ----------------
__global__ void init_k() {
    int i = blockIdx.x * blockDim.x + threadIdx.x;
    if (i < 2 * CH) g_stats[i] = 0.f;
    for (int j = i; j < NN; j += gridDim.x * blockDim.x) g_cnt[j] = 0;
}

// ---------------- batchnorm stats ----------------
__global__ void bn_stats_k(const float* __restrict__ x) {
    int c = threadIdx.x; // 128 threads
    float s = 0.f, sq = 0.f;
    for (int r = blockIdx.x; r < NN; r += gridDim.x) {
        float v = x[r * CH + c];
        s += v; sq += v * v;
    }
    atomicAdd(&g_stats[c], s);
    atomicAdd(&g_stats[CH + c], sq);
}

__global__ void bn_finalize_k(const float* __restrict__ gamma, const float* __restrict__ beta) {
    int c = threadIdx.x;
    float mean = g_stats[c] / (float)NN;
    float var = g_stats[CH + c] / (float)NN - mean * mean;
    float scale = gamma[c] * rsqrtf(var + EPS);
    g_stats[2 * CH + c] = scale;
    g_stats[3 * CH + c] = beta[c] - mean * scale;
}

// ---------------- CSR build ----------------
__global__ void hist_k(const void* __restrict__ ei) {
    int e = blockIdx.x * blockDim.x + threadIdx.x;
    if (e < NE) {
        int d = edge_at(ei, NE + e);
        if (d >= 0 && d < NN) atomicAdd(&g_cnt[d], 1);
    }
}

// phase 1: per-block exclusive scan of g_cnt chunk -> g_rowptr (block-local), block total -> g_blksum
__global__ void block_scan_k() {
    __shared__ int warpsum[32];
    int t = threadIdx.x, lane = t & 31, wid = t >> 5;
    int i = blockIdx.x * 1024 + t;
    int v = (i < NN) ? g_cnt[i] : 0;
    int x = v;
    #pragma unroll
    for (int o = 1; o < 32; o <<= 1) {
        int y = __shfl_up_sync(0xffffffffu, x, o);
        if (lane >= o) x += y;
    }
    if (lane == 31) warpsum[wid] = x;
    __syncthreads();
    if (wid == 0) {
        int w = warpsum[lane];
        #pragma unroll
        for (int o = 1; o < 32; o <<= 1) {
            int y = __shfl_up_sync(0xffffffffu, w, o);
            if (lane >= o) w += y;
        }
        warpsum[lane] = w;
    }
    __syncthreads();
    int prefix = (wid > 0) ? warpsum[wid - 1] : 0;
    int incl = x + prefix;
    if (i < NN) g_rowptr[i] = incl - v;   // block-local exclusive
    if (t == 1023) g_blksum[blockIdx.x] = incl;
}

// phase 2: scan the NB block totals -> g_blkoff, grand total -> g_rowptr[NN]
__global__ void scan_totals_k() {
    __shared__ int warpsum[4];
    int t = threadIdx.x, lane = t & 31, wid = t >> 5; // 128 threads
    int v = (t < NB) ? g_blksum[t] : 0;
    int x = v;
    #pragma unroll
    for (int o = 1; o < 32; o <<= 1) {
        int y = __shfl_up_sync(0xffffffffu, x, o);
        if (lane >= o) x += y;
    }
    if (lane == 31) warpsum[wid] = x;
    __syncthreads();
    if (t == 0) {
        int a = 0;
        #pragma unroll
        for (int k = 0; k < 4; k++) { int b = warpsum[k]; warpsum[k] = a; a += b; }
        g_rowptr[NN] = a;
    }
    __syncthreads();
    if (t < NB) g_blkoff[t] = x - v + warpsum[wid];
}

// phase 3: add block offsets, materialize rowptr + cursor
__global__ void add_offsets_k() {
    int i = blockIdx.x * 1024 + threadIdx.x;
    if (i < NN) {
        int val = g_rowptr[i] + g_blkoff[blockIdx.x];
        g_rowptr[i] = val;
        g_cursor[i] = val;
    }
}

__global__ void scatter_k(const void* __restrict__ ei) {
    int e = blockIdx.x * blockDim.x + threadIdx.x;
    if (e < NE) {
        int d = edge_at(ei, NE + e);
        int s = edge_at(ei, e);
        if (d >= 0 && d < NN && s >= 0 && s < NN) {
            int pos = atomicAdd(&g_cursor[d], 1);
            if (pos >= 0 && pos < NE) g_esrc[pos] = s;
        }
    }
}

// ---------------- tf32 tensor-core GEMM ----------------
#define LDA 132   // As row stride: conflict-free A frag loads
#define LDW 136   // Ws row stride: conflict-free B frag loads

__device__ __forceinline__ float tf32r(float x) {
    uint32_t u;
    asm("cvt.rna.tf32.f32 %0, %1;" : "=r"(u) : "f"(x));
    return __uint_as_float(u);
}

__device__ __forceinline__ void mma_tf32(float* c, const uint32_t* a, uint32_t b0, uint32_t b1) {
    asm volatile(
        "mma.sync.aligned.m16n8k8.row.col.f32.tf32.tf32.f32 "
        "{%0,%1,%2,%3}, {%4,%5,%6,%7}, {%8,%9}, {%0,%1,%2,%3};"
        : "+f"(c[0]), "+f"(c[1]), "+f"(c[2]), "+f"(c[3])
        : "r"(a[0]), "r"(a[1]), "r"(a[2]), "r"(a[3]), "r"(b0), "r"(b1));
}

__device__ __forceinline__ void stage_w(const float* __restrict__ W, float* Ws, int t) {
    #pragma unroll
    for (int i = 0; i < 16; i++) {
        int lin = i * 256 + t;
        int r = lin >> 5, c4 = lin & 31;
        float4 w = ((const float4*)W)[lin];
        w.x = tf32r(w.x); w.y = tf32r(w.y); w.z = tf32r(w.z); w.w = tf32r(w.w);
        *(float4*)&Ws[r * LDW + c4 * 4] = w;
    }
}

template <bool RESID>
__device__ __forceinline__ void mma_compute_store(const float* As, const float* Ws,
                                                  const float* __restrict__ bias,
                                                  float* __restrict__ Out,
                                                  const float* __restrict__ resid,
                                                  int row0, int t) {
    const int lane = t & 31, wrp = t >> 5;
    const int wm = wrp & 3, wn = wrp >> 2;
    const int g = lane >> 2, tg = lane & 3;

    float acc[2][8][4];
    #pragma unroll
    for (int mi = 0; mi < 2; mi++)
        #pragma unroll
        for (int nj = 0; nj < 8; nj++)
            #pragma unroll
            for (int c = 0; c < 4; c++) acc[mi][nj][c] = 0.f;

    #pragma unroll
    for (int ks = 0; ks < 16; ks++) {
        const int k0 = ks * 8;
        uint32_t a[2][4];
        #pragma unroll
        for (int mi = 0; mi < 2; mi++) {
            const float* p = As + (wm * 32 + mi * 16 + g) * LDA + k0 + tg;
            a[mi][0] = __float_as_uint(p[0]);
            a[mi][1] = __float_as_uint(p[8 * LDA]);
            a[mi][2] = __float_as_uint(p[4]);
            a[mi][3] = __float_as_uint(p[8 * LDA + 4]);
        }
        #pragma unroll
        for (int nj = 0; nj < 8; nj++) {
            const float* qp = Ws + (k0 + tg) * LDW + wn * 64 + nj * 8 + g;
            uint32_t b0 = __float_as_uint(qp[0]);
            uint32_t b1 = __float_as_uint(qp[4 * LDW]);
            mma_tf32(acc[0][nj], a[0], b0, b1);
            mma_tf32(acc[1][nj], a[1], b0, b1);
        }
    }

    #pragma unroll
    for (int mi = 0; mi < 2; mi++) {
        #pragma unroll
        for (int half = 0; half < 2; half++) {
            int gr = row0 + wm * 32 + mi * 16 + g + half * 8;
            if (gr < NN) {
                #pragma unroll
                for (int nj = 0; nj < 8; nj++) {
                    int col = wn * 64 + nj * 8 + 2 * tg;
                    float c0 = acc[mi][nj][half * 2 + 0] + __ldg(&bias[col]);
                    float c1 = acc[mi][nj][half * 2 + 1] + __ldg(&bias[col + 1]);
                    if (RESID) {
                        float2 rr = *(const float2*)&resid[gr * 128 + col];
                        c0 += rr.x; c1 += rr.y;
                    }
                    *(float2*)&Out[gr * 128 + col] = make_float2(c0, c1);
                }
            }
        }
    }
}

// fused QKVS: stage A (BN+ReLU+tf32) once, loop 4 weight sets
__global__ void __launch_bounds__(256, 1) gemm_qkvs_fused_k(
    const float* __restrict__ x,
    const float* __restrict__ Wq, const float* __restrict__ bq,
    const float* __restrict__ Wk, const float* __restrict__ bk,
    const float* __restrict__ Wv, const float* __restrict__ bv,
    const float* __restrict__ Ws_, const float* __restrict__ bs) {
    extern __shared__ float sm[];
    float* As = sm;
    float* Ws = sm + 128 * LDA;
    const int t = threadIdx.x;
    const int row0 = blockIdx.x * 128;

    #pragma unroll
    for (int i = 0; i < 16; i++) {
        int lin = i * 256 + t;
        int r = lin >> 5, c4 = lin & 31;
        int gr = row0 + r;
        float4 a = (gr < NN) ? ((const float4*)x)[gr * 32 + c4] : make_float4(0.f, 0.f, 0.f, 0.f);
        float4 sc = ((const float4*)(g_stats + 2 * CH))[c4];
        float4 sh = ((const float4*)(g_stats + 3 * CH))[c4];
        a.x = tf32r(fmaxf(0.f, a.x * sc.x + sh.x));
        a.y = tf32r(fmaxf(0.f, a.y * sc.y + sh.y));
        a.z = tf32r(fmaxf(0.f, a.z * sc.z + sh.z));
        a.w = tf32r(fmaxf(0.f, a.w * sc.w + sh.w));
        *(float4*)&As[r * LDA + c4 * 4] = a;
    }

    #pragma unroll 1
    for (int wsel = 0; wsel < 4; wsel++) {
        const float* W; const float* b; float* O;
        switch (wsel) {
            case 0: W = Wq;  b = bq; O = g_q; break;
            case 1: W = Wk;  b = bk; O = g_k; break;
            case 2: W = Wv;  b = bv; O = g_v; break;
            default: W = Ws_; b = bs; O = g_sk; break;
        }
        stage_w(W, Ws, t);
        __syncthreads();
        mma_compute_store<false>(As, Ws, b, O, nullptr, row0, t);
        __syncthreads();
    }
}

__global__ void __launch_bounds__(256, 1) gemm_final_k(
    const float* __restrict__ Wfc, const float* __restrict__ bfc,
    const float* __restrict__ x, float* __restrict__ out) {
    extern __shared__ float sm[];
    float* As = sm;
    float* Ws = sm + 128 * LDA;
    const int t = threadIdx.x;
    const int row0 = blockIdx.x * 128;
    #pragma unroll
    for (int i = 0; i < 16; i++) {
        int lin = i * 256 + t;
        int r = lin >> 5, c4 = lin & 31;
        int gr = row0 + r;
        float4 a = (gr < NN) ? ((const float4*)g_sk)[gr * 32 + c4] : make_float4(0.f, 0.f, 0.f, 0.f);
        a.x = tf32r(a.x); a.y = tf32r(a.y); a.z = tf32r(a.z); a.w = tf32r(a.w);
        *(float4*)&As[r * LDA + c4 * 4] = a;
    }
    stage_w(Wfc, Ws, t);
    __syncthreads();
    mma_compute_store<true>(As, Ws, bfc, out, x, row0, t);
}

// ---------------- attention: warp-per-node, lane = float4 chunk (head = lane>>3) ----------------
__global__ void attn_k() {
    int w = (blockIdx.x * blockDim.x + threadIdx.x) >> 5;
    int lane = threadIdx.x & 31;
    if (w >= NN) return;
    const float inv = 0.17677669529663689f; // 1/sqrt(32)
    const int off = lane * 4;               // floats [4l,4l+4); head = lane>>3
    const int base = w * CH;

    float4 q4 = *(const float4*)&g_q[base + off];
    q4.x *= inv; q4.y *= inv; q4.z *= inv; q4.w *= inv;

    int beg = g_rowptr[w], end = g_rowptr[w + 1];
    float m = -1e30f, l = 0.f;
    float4 acc = make_float4(0.f, 0.f, 0.f, 0.f);

    for (int e = beg; e < end; e++) {
        int s = __ldg(&g_esrc[e]);
        float4 k4 = *(const float4*)&g_k[s * CH + off];
        float4 v4 = *(const float4*)&g_v[s * CH + off];
        float tt = q4.x * k4.x + q4.y * k4.y + q4.z * k4.z + q4.w * k4.w;
        tt += __shfl_xor_sync(0xffffffffu, tt, 1);
        tt += __shfl_xor_sync(0xffffffffu, tt, 2);
        tt += __shfl_xor_sync(0xffffffffu, tt, 4);
        float nm = fmaxf(m, tt);
        float sc = __expf(m - nm);
        float p  = __expf(tt - nm);
        m = nm;
        l = l * sc + p;
        acc.x = acc.x * sc + p * v4.x;
        acc.y = acc.y * sc + p * v4.y;
        acc.z = acc.z * sc + p * v4.z;
        acc.w = acc.w * sc + p * v4.w;
    }
    if (l > 0.f) {
        float r = 1.f / l;
        float4 o = *(float4*)&g_sk[base + off];
        o.x += acc.x * r;
        o.y += acc.y * r;
        o.z += acc.z * r;
        o.w += acc.w * r;
        *(float4*)&g_sk[base + off] = o;
    }
}

// ---------------- launch (fork-join: CSR chain || BN+GEMM chain) ----------------
extern "C" void kernel_launch(void* const* d_in, const int* in_sizes, int n_in,
                              void* d_out, int out_size) {
    const float* x         = (const float*)d_in[0];
    const void* ei         = d_in[1];
    const float* bn_gamma  = (const float*)d_in[2];
    const float* bn_beta   = (const float*)d_in[3];
    const float* Wq        = (const float*)d_in[4];
    const float* bq        = (const float*)d_in[5];
    const float* Wk        = (const float*)d_in[6];
    const float* bk        = (const float*)d_in[7];
    const float* Wv        = (const float*)d_in[8];
    const float* bv        = (const float*)d_in[9];
    const float* Wskip     = (const float*)d_in[10];
    const float* bskip     = (const float*)d_in[11];
    const float* Wfc       = (const float*)d_in[12];
    const float* bfc       = (const float*)d_in[13];
    float* out = (float*)d_out;

    static cudaStream_t s_side = nullptr;
    static cudaEvent_t ev_fork = nullptr, ev_join = nullptr;
    if (s_side == nullptr) {
        cudaStreamCreateWithFlags(&s_side, cudaStreamNonBlocking);
        cudaEventCreateWithFlags(&ev_fork, cudaEventDisableTiming);
        cudaEventCreateWithFlags(&ev_join, cudaEventDisableTiming);
    }

    const int SMEM = (128 * LDA + 128 * LDW) * 4;  // 137216 B
    cudaFuncSetAttribute(gemm_qkvs_fused_k, cudaFuncAttributeMaxDynamicSharedMemorySize, SMEM);
    cudaFuncSetAttribute(gemm_final_k, cudaFuncAttributeMaxDynamicSharedMemorySize, SMEM);

    const int MBLK = (NN + 127) / 128; // 782

    // common prologue (main stream)
    detect_k<<<1, 32>>>((const long long*)ei);
    init_k<<<256, 256>>>();

    // fork: CSR chain on side stream
    cudaEventRecord(ev_fork, 0);
    cudaStreamWaitEvent(s_side, ev_fork, 0);
    hist_k<<<(NE + 255) / 256, 256, 0, s_side>>>(ei);
    block_scan_k<<<NB, 1024, 0, s_side>>>();
    scan_totals_k<<<1, 128, 0, s_side>>>();
    add_offsets_k<<<NB, 1024, 0, s_side>>>();
    scatter_k<<<(NE + 255) / 256, 256, 0, s_side>>>(ei);
    cudaEventRecord(ev_join, s_side);

    // main chain: BN + fused QKVS GEMM
    bn_stats_k<<<512, 128>>>(x);
    bn_finalize_k<<<1, 128>>>(bn_gamma, bn_beta);
    gemm_qkvs_fused_k<<<MBLK, 256, SMEM>>>(x, Wq, bq, Wk, bk, Wv, bv, Wskip, bskip);

    // join: attention needs CSR + q/k/v/skip
    cudaStreamWaitEvent(0, ev_join, 0);
    attn_k<<<(NN * 32 + 255) / 256, 256>>>();
    gemm_final_k<<<MBLK, 256, SMEM>>>(Wfc, bfc, x, out);
}

// round 8
// speedup vs baseline: 2.1899x; 1.1106x over previous
#include <cuda_runtime.h>
#include <cuda_fp16.h>
#include <math.h>
#include <stdint.h>

#define NN 100000
#define NE 1600000
#define CH 128          // channels = H*D
#define NH 4
#define HD 32
#define EPS 1e-5f
#define NB 98           // ceil(NN/1024) scan blocks

// ---------------- scratch (device globals; no allocation allowed) ----------------
__device__ __align__(128) float g_q[NN * CH];
__device__ __align__(128) __half g_kv[NN * 2 * CH];  // per node: 32 chunks of [4 half k | 4 half v]
__device__ __align__(128) float g_sk[NN * CH];   // skip, then conv (in-place)
__device__ __align__(128) float g_stats[4 * CH]; // sum, sumsq, scale, shift
__device__ int g_cnt[NN];
__device__ int g_rowptr[NN + 1];
__device__ int g_cursor[NN];
__device__ int g_esrc[NE];
__device__ int g_blksum[128];
__device__ int g_blkoff[128];
__device__ int g_is64;

// ---------------- edge dtype detection ----------------
__global__ void detect_k(const long long* __restrict__ ei) {
    if (threadIdx.x == 0) {
        int ok = 1;
        for (int i = 0; i < 256; i++) {
            long long v = ei[i];
            if (v < 0 || v >= NN) { ok = 0; break; }
        }
        g_is64 = ok;
    }
}

__device__ __forceinline__ int edge_at(const void* ei, int idx) {
    return g_is64 ? (int)((const long long*)ei)[idx] : ((const int*)ei)[idx];
}

// ---------------- init ----------------
__global__ void init_k() {
    int i = blockIdx.x * blockDim.x + threadIdx.x;
    if (i < 2 * CH) g_stats[i] = 0.f;
    for (int j = i; j < NN; j += gridDim.x * blockDim.x) g_cnt[j] = 0;
}

// ---------------- batchnorm stats ----------------
__global__ void bn_stats_k(const float* __restrict__ x) {
    int c = threadIdx.x; // 128 threads
    float s = 0.f, sq = 0.f;
    for (int r = blockIdx.x; r < NN; r += gridDim.x) {
        float v = x[r * CH + c];
        s += v; sq += v * v;
    }
    atomicAdd(&g_stats[c], s);
    atomicAdd(&g_stats[CH + c], sq);
}

__global__ void bn_finalize_k(const float* __restrict__ gamma, const float* __restrict__ beta) {
    int c = threadIdx.x;
    float mean = g_stats[c] / (float)NN;
    float var = g_stats[CH + c] / (float)NN - mean * mean;
    float scale = gamma[c] * rsqrtf(var + EPS);
    g_stats[2 * CH + c] = scale;
    g_stats[3 * CH + c] = beta[c] - mean * scale;
}

// ---------------- CSR build ----------------
__global__ void hist_k(const void* __restrict__ ei) {
    int e = blockIdx.x * blockDim.x + threadIdx.x;
    if (e < NE) {
        int d = edge_at(ei, NE + e);
        if (d >= 0 && d < NN) atomicAdd(&g_cnt[d], 1);
    }
}

__global__ void block_scan_k() {
    __shared__ int warpsum[32];
    int t = threadIdx.x, lane = t & 31, wid = t >> 5;
    int i = blockIdx.x * 1024 + t;
    int v = (i < NN) ? g_cnt[i] : 0;
    int x = v;
    #pragma unroll
    for (int o = 1; o < 32; o <<= 1) {
        int y = __shfl_up_sync(0xffffffffu, x, o);
        if (lane >= o) x += y;
    }
    if (lane == 31) warpsum[wid] = x;
    __syncthreads();
    if (wid == 0) {
        int w = warpsum[lane];
        #pragma unroll
        for (int o = 1; o < 32; o <<= 1) {
            int y = __shfl_up_sync(0xffffffffu, w, o);
            if (lane >= o) w += y;
        }
        warpsum[lane] = w;
    }
    __syncthreads();
    int prefix = (wid > 0) ? warpsum[wid - 1] : 0;
    int incl = x + prefix;
    if (i < NN) g_rowptr[i] = incl - v;
    if (t == 1023) g_blksum[blockIdx.x] = incl;
}

__global__ void scan_totals_k() {
    __shared__ int warpsum[4];
    int t = threadIdx.x, lane = t & 31, wid = t >> 5; // 128 threads
    int v = (t < NB) ? g_blksum[t] : 0;
    int x = v;
    #pragma unroll
    for (int o = 1; o < 32; o <<= 1) {
        int y = __shfl_up_sync(0xffffffffu, x, o);
        if (lane >= o) x += y;
    }
    if (lane == 31) warpsum[wid] = x;
    __syncthreads();
    if (t == 0) {
        int a = 0;
        #pragma unroll
        for (int k = 0; k < 4; k++) { int b = warpsum[k]; warpsum[k] = a; a += b; }
        g_rowptr[NN] = a;
    }
    __syncthreads();
    if (t < NB) g_blkoff[t] = x - v + warpsum[wid];
}

__global__ void add_offsets_k() {
    int i = blockIdx.x * 1024 + threadIdx.x;
    if (i < NN) {
        int val = g_rowptr[i] + g_blkoff[blockIdx.x];
        g_rowptr[i] = val;
        g_cursor[i] = val;
    }
}

__global__ void scatter_k(const void* __restrict__ ei) {
    int e = blockIdx.x * blockDim.x + threadIdx.x;
    if (e < NE) {
        int d = edge_at(ei, NE + e);
        int s = edge_at(ei, e);
        if (d >= 0 && d < NN && s >= 0 && s < NN) {
            int pos = atomicAdd(&g_cursor[d], 1);
            if (pos >= 0 && pos < NE) g_esrc[pos] = s;
        }
    }
}

// ---------------- tf32 tensor-core GEMM ----------------
#define LDA 132
#define LDW 136

__device__ __forceinline__ float tf32r(float x) {
    uint32_t u;
    asm("cvt.rna.tf32.f32 %0, %1;" : "=r"(u) : "f"(x));
    return __uint_as_float(u);
}

__device__ __forceinline__ void mma_tf32(float* c, const uint32_t* a, uint32_t b0, uint32_t b1) {
    asm volatile(
        "mma.sync.aligned.m16n8k8.row.col.f32.tf32.tf32.f32 "
        "{%0,%1,%2,%3}, {%4,%5,%6,%7}, {%8,%9}, {%0,%1,%2,%3};"
        : "+f"(c[0]), "+f"(c[1]), "+f"(c[2]), "+f"(c[3])
        : "r"(a[0]), "r"(a[1]), "r"(a[2]), "r"(a[3]), "r"(b0), "r"(b1));
}

__device__ __forceinline__ void stage_w(const float* __restrict__ W, float* Ws, int t) {
    #pragma unroll
    for (int i = 0; i < 16; i++) {
        int lin = i * 256 + t;
        int r = lin >> 5, c4 = lin & 31;
        float4 w = ((const float4*)W)[lin];
        w.x = tf32r(w.x); w.y = tf32r(w.y); w.z = tf32r(w.z); w.w = tf32r(w.w);
        *(float4*)&Ws[r * LDW + c4 * 4] = w;
    }
}

// OUTMODE: 0 = fp32 plain, 1 = fp32 + residual, 2 = fp16 into g_kv (kvoff 0=k, 4=v)
template <int OUTMODE>
__device__ __forceinline__ void mma_compute_store(const float* As, const float* Ws,
                                                  const float* __restrict__ bias,
                                                  float* __restrict__ Out,
                                                  const float* __restrict__ resid,
                                                  int row0, int t, int kvoff) {
    const int lane = t & 31, wrp = t >> 5;
    const int wm = wrp & 3, wn = wrp >> 2;
    const int g = lane >> 2, tg = lane & 3;

    float acc[2][8][4];
    #pragma unroll
    for (int mi = 0; mi < 2; mi++)
        #pragma unroll
        for (int nj = 0; nj < 8; nj++)
            #pragma unroll
            for (int c = 0; c < 4; c++) acc[mi][nj][c] = 0.f;

    #pragma unroll
    for (int ks = 0; ks < 16; ks++) {
        const int k0 = ks * 8;
        uint32_t a[2][4];
        #pragma unroll
        for (int mi = 0; mi < 2; mi++) {
            const float* p = As + (wm * 32 + mi * 16 + g) * LDA + k0 + tg;
            a[mi][0] = __float_as_uint(p[0]);
            a[mi][1] = __float_as_uint(p[8 * LDA]);
            a[mi][2] = __float_as_uint(p[4]);
            a[mi][3] = __float_as_uint(p[8 * LDA + 4]);
        }
        #pragma unroll
        for (int nj = 0; nj < 8; nj++) {
            const float* qp = Ws + (k0 + tg) * LDW + wn * 64 + nj * 8 + g;
            uint32_t b0 = __float_as_uint(qp[0]);
            uint32_t b1 = __float_as_uint(qp[4 * LDW]);
            mma_tf32(acc[0][nj], a[0], b0, b1);
            mma_tf32(acc[1][nj], a[1], b0, b1);
        }
    }

    #pragma unroll
    for (int mi = 0; mi < 2; mi++) {
        #pragma unroll
        for (int half_ = 0; half_ < 2; half_++) {
            int gr = row0 + wm * 32 + mi * 16 + g + half_ * 8;
            if (gr < NN) {
                #pragma unroll
                for (int nj = 0; nj < 8; nj++) {
                    int col = wn * 64 + nj * 8 + 2 * tg;
                    float c0 = acc[mi][nj][half_ * 2 + 0] + __ldg(&bias[col]);
                    float c1 = acc[mi][nj][half_ * 2 + 1] + __ldg(&bias[col + 1]);
                    if (OUTMODE == 1) {
                        float2 rr = *(const float2*)&resid[gr * 128 + col];
                        c0 += rr.x; c1 += rr.y;
                    }
                    if (OUTMODE == 2) {
                        // interleaved kv: node*256 + chunk*8 + kvoff + (col&3)
                        int addr = gr * 256 + (col >> 2) * 8 + kvoff + (col & 3);
                        *(__half2*)&g_kv[addr] = __floats2half2_rn(c0, c1);
                    } else {
                        *(float2*)&Out[gr * 128 + col] = make_float2(c0, c1);
                    }
                }
            }
        }
    }
}

// fused QKVS: stage A (BN+ReLU+tf32) once, loop 4 weight sets
__global__ void __launch_bounds__(256, 1) gemm_qkvs_fused_k(
    const float* __restrict__ x,
    const float* __restrict__ Wq, const float* __restrict__ bq,
    const float* __restrict__ Wk, const float* __restrict__ bk,
    const float* __restrict__ Wv, const float* __restrict__ bv,
    const float* __restrict__ Ws_, const float* __restrict__ bs) {
    extern __shared__ float sm[];
    float* As = sm;
    float* Ws = sm + 128 * LDA;
    const int t = threadIdx.x;
    const int row0 = blockIdx.x * 128;

    #pragma unroll
    for (int i = 0; i < 16; i++) {
        int lin = i * 256 + t;
        int r = lin >> 5, c4 = lin & 31;
        int gr = row0 + r;
        float4 a = (gr < NN) ? ((const float4*)x)[gr * 32 + c4] : make_float4(0.f, 0.f, 0.f, 0.f);
        float4 sc = ((const float4*)(g_stats + 2 * CH))[c4];
        float4 sh = ((const float4*)(g_stats + 3 * CH))[c4];
        a.x = tf32r(fmaxf(0.f, a.x * sc.x + sh.x));
        a.y = tf32r(fmaxf(0.f, a.y * sc.y + sh.y));
        a.z = tf32r(fmaxf(0.f, a.z * sc.z + sh.z));
        a.w = tf32r(fmaxf(0.f, a.w * sc.w + sh.w));
        *(float4*)&As[r * LDA + c4 * 4] = a;
    }

    // q (fp32)
    stage_w(Wq, Ws, t);
    __syncthreads();
    mma_compute_store<0>(As, Ws, bq, g_q, nullptr, row0, t, 0);
    __syncthreads();
    // k (fp16 -> g_kv offset 0)
    stage_w(Wk, Ws, t);
    __syncthreads();
    mma_compute_store<2>(As, Ws, bk, nullptr, nullptr, row0, t, 0);
    __syncthreads();
    // v (fp16 -> g_kv offset 4)
    stage_w(Wv, Ws, t);
    __syncthreads();
    mma_compute_store<2>(As, Ws, bv, nullptr, nullptr, row0, t, 4);
    __syncthreads();
    // skip (fp32)
    stage_w(Ws_, Ws, t);
    __syncthreads();
    mma_compute_store<0>(As, Ws, bs, g_sk, nullptr, row0, t, 0);
}

__global__ void __launch_bounds__(256, 1) gemm_final_k(
    const float* __restrict__ Wfc, const float* __restrict__ bfc,
    const float* __restrict__ x, float* __restrict__ out) {
    extern __shared__ float sm[];
    float* As = sm;
    float* Ws = sm + 128 * LDA;
    const int t = threadIdx.x;
    const int row0 = blockIdx.x * 128;
    #pragma unroll
    for (int i = 0; i < 16; i++) {
        int lin = i * 256 + t;
        int r = lin >> 5, c4 = lin & 31;
        int gr = row0 + r;
        float4 a = (gr < NN) ? ((const float4*)g_sk)[gr * 32 + c4] : make_float4(0.f, 0.f, 0.f, 0.f);
        a.x = tf32r(a.x); a.y = tf32r(a.y); a.z = tf32r(a.z); a.w = tf32r(a.w);
        *(float4*)&As[r * LDA + c4 * 4] = a;
    }
    stage_w(Wfc, Ws, t);
    __syncthreads();
    mma_compute_store<1>(As, Ws, bfc, out, x, row0, t, 0);
}

// ---------------- attention: warp-per-node, lane = float4 chunk, fp16 interleaved kv ----------------
__global__ void attn_k() {
    int w = (blockIdx.x * blockDim.x + threadIdx.x) >> 5;
    int lane = threadIdx.x & 31;
    if (w >= NN) return;
    const float inv = 0.17677669529663689f; // 1/sqrt(32)
    const int off = lane * 4;               // floats [4l,4l+4); head = lane>>3
    const int base = w * CH;

    float4 q4 = *(const float4*)&g_q[base + off];
    q4.x *= inv; q4.y *= inv; q4.z *= inv; q4.w *= inv;

    int beg = g_rowptr[w], end = g_rowptr[w + 1];
    float m = -1e30f, l = 0.f;
    float4 acc = make_float4(0.f, 0.f, 0.f, 0.f);

    for (int e = beg; e < end; e++) {
        int s = __ldg(&g_esrc[e]);
        // one 16B load: 4 half k + 4 half v for this lane's chunk
        uint4 kv = *(const uint4*)&g_kv[s * 256 + lane * 8];
        float2 k01 = __half22float2(*(__half2*)&kv.x);
        float2 k23 = __half22float2(*(__half2*)&kv.y);
        float2 v01 = __half22float2(*(__half2*)&kv.z);
        float2 v23 = __half22float2(*(__half2*)&kv.w);
        float tt = q4.x * k01.x + q4.y * k01.y + q4.z * k23.x + q4.w * k23.y;
        tt += __shfl_xor_sync(0xffffffffu, tt, 1);
        tt += __shfl_xor_sync(0xffffffffu, tt, 2);
        tt += __shfl_xor_sync(0xffffffffu, tt, 4);
        float nm = fmaxf(m, tt);
        float sc = __expf(m - nm);
        float p  = __expf(tt - nm);
        m = nm;
        l = l * sc + p;
        acc.x = acc.x * sc + p * v01.x;
        acc.y = acc.y * sc + p * v01.y;
        acc.z = acc.z * sc + p * v23.x;
        acc.w = acc.w * sc + p * v23.y;
    }
    if (l > 0.f) {
        float r = 1.f / l;
        float4 o = *(float4*)&g_sk[base + off];
        o.x += acc.x * r;
        o.y += acc.y * r;
        o.z += acc.z * r;
        o.w += acc.w * r;
        *(float4*)&g_sk[base + off] = o;
    }
}

// ---------------- launch (fork-join: CSR chain || BN+GEMM chain) ----------------
extern "C" void kernel_launch(void* const* d_in, const int* in_sizes, int n_in,
                              void* d_out, int out_size) {
    const float* x         = (const float*)d_in[0];
    const void* ei         = d_in[1];
    const float* bn_gamma  = (const float*)d_in[2];
    const float* bn_beta   = (const float*)d_in[3];
    const float* Wq        = (const float*)d_in[4];
    const float* bq        = (const float*)d_in[5];
    const float* Wk        = (const float*)d_in[6];
    const float* bk        = (const float*)d_in[7];
    const float* Wv        = (const float*)d_in[8];
    const float* bv        = (const float*)d_in[9];
    const float* Wskip     = (const float*)d_in[10];
    const float* bskip     = (const float*)d_in[11];
    const float* Wfc       = (const float*)d_in[12];
    const float* bfc       = (const float*)d_in[13];
    float* out = (float*)d_out;

    static cudaStream_t s_side = nullptr;
    static cudaEvent_t ev_fork = nullptr, ev_join = nullptr;
    if (s_side == nullptr) {
        cudaStreamCreateWithFlags(&s_side, cudaStreamNonBlocking);
        cudaEventCreateWithFlags(&ev_fork, cudaEventDisableTiming);
        cudaEventCreateWithFlags(&ev_join, cudaEventDisableTiming);
    }

    const int SMEM = (128 * LDA + 128 * LDW) * 4;  // 137216 B
    cudaFuncSetAttribute(gemm_qkvs_fused_k, cudaFuncAttributeMaxDynamicSharedMemorySize, SMEM);
    cudaFuncSetAttribute(gemm_final_k, cudaFuncAttributeMaxDynamicSharedMemorySize, SMEM);

    const int MBLK = (NN + 127) / 128; // 782

    detect_k<<<1, 32>>>((const long long*)ei);
    init_k<<<256, 256>>>();

    // fork: CSR chain on side stream
    cudaEventRecord(ev_fork, 0);
    cudaStreamWaitEvent(s_side, ev_fork, 0);
    hist_k<<<(NE + 255) / 256, 256, 0, s_side>>>(ei);
    block_scan_k<<<NB, 1024, 0, s_side>>>();
    scan_totals_k<<<1, 128, 0, s_side>>>();
    add_offsets_k<<<NB, 1024, 0, s_side>>>();
    scatter_k<<<(NE + 255) / 256, 256, 0, s_side>>>(ei);
    cudaEventRecord(ev_join, s_side);

    // main chain: BN + fused QKVS GEMM
    bn_stats_k<<<512, 128>>>(x);
    bn_finalize_k<<<1, 128>>>(bn_gamma, bn_beta);
    gemm_qkvs_fused_k<<<MBLK, 256, SMEM>>>(x, Wq, bq, Wk, bk, Wv, bv, Wskip, bskip);

    // join: attention needs CSR + q/kv/skip
    cudaStreamWaitEvent(0, ev_join, 0);
    attn_k<<<(NN * 32 + 255) / 256, 256>>>();
    gemm_final_k<<<MBLK, 256, SMEM>>>(Wfc, bfc, x, out);
}

// round 9
// speedup vs baseline: 2.2415x; 1.0236x over previous
#include <cuda_runtime.h>
#include <cuda_fp16.h>
#include <math.h>
#include <stdint.h>

#define NN 100000
#define NE 1600000
#define CH 128          // channels = H*D
#define NH 4
#define HD 32
#define EPS 1e-5f
#define NB 98           // ceil(NN/1024) scan blocks

// ---------------- scratch (device globals; no allocation allowed) ----------------
__device__ __align__(128) float g_q[NN * CH];
__device__ __align__(128) __half g_kv[NN * 2 * CH];  // per node: 32 chunks of [4 half k | 4 half v]
__device__ __align__(128) float g_sk[NN * CH];   // skip, then conv (in-place)
__device__ __align__(128) float g_stats[4 * CH]; // sum, sumsq, scale, shift
__device__ int g_cnt[NN];
__device__ int g_rowptr[NN + 1];
__device__ int g_cursor[NN];
__device__ int g_esrc[NE];
__device__ int g_blksum[128];
__device__ int g_blkoff[128];
__device__ int g_is64;

// ---------------- edge dtype detection (one warp, parallel) ----------------
__global__ void detect_k(const long long* __restrict__ ei) {
    int lane = threadIdx.x;
    int bad = 0;
    #pragma unroll
    for (int i = 0; i < 8; i++) {
        long long v = ei[lane + i * 32];
        bad |= (v < 0 || v >= NN) ? 1 : 0;
    }
    bad = __any_sync(0xffffffffu, bad);
    if (lane == 0) g_is64 = !bad;
}

__device__ __forceinline__ int edge_at(const void* ei, int idx) {
    return g_is64 ? (int)((const long long*)ei)[idx] : ((const int*)ei)[idx];
}

// ---------------- init ----------------
__global__ void init_k() {
    int i = blockIdx.x * blockDim.x + threadIdx.x;
    if (i < 2 * CH) g_stats[i] = 0.f;
    for (int j = i; j < NN; j += gridDim.x * blockDim.x) g_cnt[j] = 0;
}

// ---------------- batchnorm stats ----------------
__global__ void bn_stats_k(const float* __restrict__ x) {
    int c = threadIdx.x; // 128 threads
    float s = 0.f, sq = 0.f;
    for (int r = blockIdx.x; r < NN; r += gridDim.x) {
        float v = x[r * CH + c];
        s += v; sq += v * v;
    }
    atomicAdd(&g_stats[c], s);
    atomicAdd(&g_stats[CH + c], sq);
}

__global__ void bn_finalize_k(const float* __restrict__ gamma, const float* __restrict__ beta) {
    int c = threadIdx.x;
    float mean = g_stats[c] / (float)NN;
    float var = g_stats[CH + c] / (float)NN - mean * mean;
    float scale = gamma[c] * rsqrtf(var + EPS);
    g_stats[2 * CH + c] = scale;
    g_stats[3 * CH + c] = beta[c] - mean * scale;
}

// ---------------- CSR build ----------------
__global__ void hist_k(const void* __restrict__ ei) {
    int e = blockIdx.x * blockDim.x + threadIdx.x;
    if (e < NE) {
        int d = edge_at(ei, NE + e);
        if (d >= 0 && d < NN) atomicAdd(&g_cnt[d], 1);
    }
}

__global__ void block_scan_k() {
    __shared__ int warpsum[32];
    int t = threadIdx.x, lane = t & 31, wid = t >> 5;
    int i = blockIdx.x * 1024 + t;
    int v = (i < NN) ? g_cnt[i] : 0;
    int x = v;
    #pragma unroll
    for (int o = 1; o < 32; o <<= 1) {
        int y = __shfl_up_sync(0xffffffffu, x, o);
        if (lane >= o) x += y;
    }
    if (lane == 31) warpsum[wid] = x;
    __syncthreads();
    if (wid == 0) {
        int w = warpsum[lane];
        #pragma unroll
        for (int o = 1; o < 32; o <<= 1) {
            int y = __shfl_up_sync(0xffffffffu, w, o);
            if (lane >= o) w += y;
        }
        warpsum[lane] = w;
    }
    __syncthreads();
    int prefix = (wid > 0) ? warpsum[wid - 1] : 0;
    int incl = x + prefix;
    if (i < NN) g_rowptr[i] = incl - v;
    if (t == 1023) g_blksum[blockIdx.x] = incl;
}

__global__ void scan_totals_k() {
    __shared__ int warpsum[4];
    int t = threadIdx.x, lane = t & 31, wid = t >> 5; // 128 threads
    int v = (t < NB) ? g_blksum[t] : 0;
    int x = v;
    #pragma unroll
    for (int o = 1; o < 32; o <<= 1) {
        int y = __shfl_up_sync(0xffffffffu, x, o);
        if (lane >= o) x += y;
    }
    if (lane == 31) warpsum[wid] = x;
    __syncthreads();
    if (t == 0) {
        int a = 0;
        #pragma unroll
        for (int k = 0; k < 4; k++) { int b = warpsum[k]; warpsum[k] = a; a += b; }
        g_rowptr[NN] = a;
    }
    __syncthreads();
    if (t < NB) g_blkoff[t] = x - v + warpsum[wid];
}

__global__ void add_offsets_k() {
    int i = blockIdx.x * 1024 + threadIdx.x;
    if (i < NN) {
        int val = g_rowptr[i] + g_blkoff[blockIdx.x];
        g_rowptr[i] = val;
        g_cursor[i] = val;
    }
}

__global__ void scatter_k(const void* __restrict__ ei) {
    int e = blockIdx.x * blockDim.x + threadIdx.x;
    if (e < NE) {
        int d = edge_at(ei, NE + e);
        int s = edge_at(ei, e);
        if (d >= 0 && d < NN && s >= 0 && s < NN) {
            int pos = atomicAdd(&g_cursor[d], 1);
            if (pos >= 0 && pos < NE) g_esrc[pos] = s;
        }
    }
}

// ---------------- tf32 tensor-core GEMM ----------------
#define LDA 132
#define LDW 136

__device__ __forceinline__ float tf32r(float x) {
    uint32_t u;
    asm("cvt.rna.tf32.f32 %0, %1;" : "=r"(u) : "f"(x));
    return __uint_as_float(u);
}

__device__ __forceinline__ void mma_tf32(float* c, const uint32_t* a, uint32_t b0, uint32_t b1) {
    asm volatile(
        "mma.sync.aligned.m16n8k8.row.col.f32.tf32.tf32.f32 "
        "{%0,%1,%2,%3}, {%4,%5,%6,%7}, {%8,%9}, {%0,%1,%2,%3};"
        : "+f"(c[0]), "+f"(c[1]), "+f"(c[2]), "+f"(c[3])
        : "r"(a[0]), "r"(a[1]), "r"(a[2]), "r"(a[3]), "r"(b0), "r"(b1));
}

__device__ __forceinline__ void stage_w(const float* __restrict__ W, float* Ws, int t) {
    #pragma unroll
    for (int i = 0; i < 16; i++) {
        int lin = i * 256 + t;
        int r = lin >> 5, c4 = lin & 31;
        float4 w = ((const float4*)W)[lin];
        w.x = tf32r(w.x); w.y = tf32r(w.y); w.z = tf32r(w.z); w.w = tf32r(w.w);
        *(float4*)&Ws[r * LDW + c4 * 4] = w;
    }
}

// OUTMODE: 0 = fp32 plain, 1 = fp32 + residual, 2 = fp16 into g_kv (kvoff 0=k, 4=v)
template <int OUTMODE>
__device__ __forceinline__ void mma_compute_store(const float* As, const float* Ws,
                                                  const float* __restrict__ bias,
                                                  float* __restrict__ Out,
                                                  const float* __restrict__ resid,
                                                  int row0, int t, int kvoff) {
    const int lane = t & 31, wrp = t >> 5;
    const int wm = wrp & 3, wn = wrp >> 2;
    const int g = lane >> 2, tg = lane & 3;

    float acc[2][8][4];
    #pragma unroll
    for (int mi = 0; mi < 2; mi++)
        #pragma unroll
        for (int nj = 0; nj < 8; nj++)
            #pragma unroll
            for (int c = 0; c < 4; c++) acc[mi][nj][c] = 0.f;

    #pragma unroll
    for (int ks = 0; ks < 16; ks++) {
        const int k0 = ks * 8;
        uint32_t a[2][4];
        #pragma unroll
        for (int mi = 0; mi < 2; mi++) {
            const float* p = As + (wm * 32 + mi * 16 + g) * LDA + k0 + tg;
            a[mi][0] = __float_as_uint(p[0]);
            a[mi][1] = __float_as_uint(p[8 * LDA]);
            a[mi][2] = __float_as_uint(p[4]);
            a[mi][3] = __float_as_uint(p[8 * LDA + 4]);
        }
        #pragma unroll
        for (int nj = 0; nj < 8; nj++) {
            const float* qp = Ws + (k0 + tg) * LDW + wn * 64 + nj * 8 + g;
            uint32_t b0 = __float_as_uint(qp[0]);
            uint32_t b1 = __float_as_uint(qp[4 * LDW]);
            mma_tf32(acc[0][nj], a[0], b0, b1);
            mma_tf32(acc[1][nj], a[1], b0, b1);
        }
    }

    #pragma unroll
    for (int mi = 0; mi < 2; mi++) {
        #pragma unroll
        for (int half_ = 0; half_ < 2; half_++) {
            int gr = row0 + wm * 32 + mi * 16 + g + half_ * 8;
            if (gr < NN) {
                #pragma unroll
                for (int nj = 0; nj < 8; nj++) {
                    int col = wn * 64 + nj * 8 + 2 * tg;
                    float c0 = acc[mi][nj][half_ * 2 + 0] + __ldg(&bias[col]);
                    float c1 = acc[mi][nj][half_ * 2 + 1] + __ldg(&bias[col + 1]);
                    if (OUTMODE == 1) {
                        float2 rr = *(const float2*)&resid[gr * 128 + col];
                        c0 += rr.x; c1 += rr.y;
                    }
                    if (OUTMODE == 2) {
                        int addr = gr * 256 + (col >> 2) * 8 + kvoff + (col & 3);
                        *(__half2*)&g_kv[addr] = __floats2half2_rn(c0, c1);
                    } else {
                        *(float2*)&Out[gr * 128 + col] = make_float2(c0, c1);
                    }
                }
            }
        }
    }
}

// fused QKVS: stage A (BN+ReLU+tf32) once, loop 4 weight sets
__global__ void __launch_bounds__(256, 1) gemm_qkvs_fused_k(
    const float* __restrict__ x,
    const float* __restrict__ Wq, const float* __restrict__ bq,
    const float* __restrict__ Wk, const float* __restrict__ bk,
    const float* __restrict__ Wv, const float* __restrict__ bv,
    const float* __restrict__ Ws_, const float* __restrict__ bs) {
    extern __shared__ float sm[];
    float* As = sm;
    float* Ws = sm + 128 * LDA;
    const int t = threadIdx.x;
    const int row0 = blockIdx.x * 128;

    #pragma unroll
    for (int i = 0; i < 16; i++) {
        int lin = i * 256 + t;
        int r = lin >> 5, c4 = lin & 31;
        int gr = row0 + r;
        float4 a = (gr < NN) ? ((const float4*)x)[gr * 32 + c4] : make_float4(0.f, 0.f, 0.f, 0.f);
        float4 sc = ((const float4*)(g_stats + 2 * CH))[c4];
        float4 sh = ((const float4*)(g_stats + 3 * CH))[c4];
        a.x = tf32r(fmaxf(0.f, a.x * sc.x + sh.x));
        a.y = tf32r(fmaxf(0.f, a.y * sc.y + sh.y));
        a.z = tf32r(fmaxf(0.f, a.z * sc.z + sh.z));
        a.w = tf32r(fmaxf(0.f, a.w * sc.w + sh.w));
        *(float4*)&As[r * LDA + c4 * 4] = a;
    }

    // q (fp32)
    stage_w(Wq, Ws, t);
    __syncthreads();
    mma_compute_store<0>(As, Ws, bq, g_q, nullptr, row0, t, 0);
    __syncthreads();
    // k (fp16 -> g_kv offset 0)
    stage_w(Wk, Ws, t);
    __syncthreads();
    mma_compute_store<2>(As, Ws, bk, nullptr, nullptr, row0, t, 0);
    __syncthreads();
    // v (fp16 -> g_kv offset 4)
    stage_w(Wv, Ws, t);
    __syncthreads();
    mma_compute_store<2>(As, Ws, bv, nullptr, nullptr, row0, t, 4);
    __syncthreads();
    // skip (fp32)
    stage_w(Ws_, Ws, t);
    __syncthreads();
    mma_compute_store<0>(As, Ws, bs, g_sk, nullptr, row0, t, 0);
}

__global__ void __launch_bounds__(256, 1) gemm_final_k(
    const float* __restrict__ Wfc, const float* __restrict__ bfc,
    const float* __restrict__ x, float* __restrict__ out) {
    extern __shared__ float sm[];
    float* As = sm;
    float* Ws = sm + 128 * LDA;
    const int t = threadIdx.x;
    const int row0 = blockIdx.x * 128;
    #pragma unroll
    for (int i = 0; i < 16; i++) {
        int lin = i * 256 + t;
        int r = lin >> 5, c4 = lin & 31;
        int gr = row0 + r;
        float4 a = (gr < NN) ? ((const float4*)g_sk)[gr * 32 + c4] : make_float4(0.f, 0.f, 0.f, 0.f);
        a.x = tf32r(a.x); a.y = tf32r(a.y); a.z = tf32r(a.z); a.w = tf32r(a.w);
        *(float4*)&As[r * LDA + c4 * 4] = a;
    }
    stage_w(Wfc, Ws, t);
    __syncthreads();
    mma_compute_store<1>(As, Ws, bfc, out, x, row0, t, 0);
}

// ---------------- attention: warp-per-node, dual online-softmax accumulators ----------------
__global__ void attn_k() {
    int w = (blockIdx.x * blockDim.x + threadIdx.x) >> 5;
    int lane = threadIdx.x & 31;
    if (w >= NN) return;
    const float inv = 0.17677669529663689f; // 1/sqrt(32)
    const int off = lane * 4;               // floats [4l,4l+4); head = lane>>3
    const int base = w * CH;

    float4 q4 = *(const float4*)&g_q[base + off];
    q4.x *= inv; q4.y *= inv; q4.z *= inv; q4.w *= inv;

    int beg = g_rowptr[w], end = g_rowptr[w + 1];

    // two independent online-softmax states (halve the serial chain)
    float m0 = -1e30f, l0 = 0.f, m1 = -1e30f, l1 = 0.f;
    float4 A0 = make_float4(0.f, 0.f, 0.f, 0.f);
    float4 A1 = make_float4(0.f, 0.f, 0.f, 0.f);

    int e = beg;
    for (; e + 1 < end; e += 2) {
        int s0 = __ldg(&g_esrc[e]);
        int s1 = __ldg(&g_esrc[e + 1]);
        uint4 kv0 = *(const uint4*)&g_kv[s0 * 256 + lane * 8];
        uint4 kv1 = *(const uint4*)&g_kv[s1 * 256 + lane * 8];

        float2 ka0 = __half22float2(*(__half2*)&kv0.x);
        float2 kb0 = __half22float2(*(__half2*)&kv0.y);
        float2 ka1 = __half22float2(*(__half2*)&kv1.x);
        float2 kb1 = __half22float2(*(__half2*)&kv1.y);
        float t0 = q4.x * ka0.x + q4.y * ka0.y + q4.z * kb0.x + q4.w * kb0.y;
        float t1 = q4.x * ka1.x + q4.y * ka1.y + q4.z * kb1.x + q4.w * kb1.y;
        t0 += __shfl_xor_sync(0xffffffffu, t0, 1);
        t1 += __shfl_xor_sync(0xffffffffu, t1, 1);
        t0 += __shfl_xor_sync(0xffffffffu, t0, 2);
        t1 += __shfl_xor_sync(0xffffffffu, t1, 2);
        t0 += __shfl_xor_sync(0xffffffffu, t0, 4);
        t1 += __shfl_xor_sync(0xffffffffu, t1, 4);

        float2 va0 = __half22float2(*(__half2*)&kv0.z);
        float2 vb0 = __half22float2(*(__half2*)&kv0.w);
        float2 va1 = __half22float2(*(__half2*)&kv1.z);
        float2 vb1 = __half22float2(*(__half2*)&kv1.w);

        float nm0 = fmaxf(m0, t0);
        float nm1 = fmaxf(m1, t1);
        float sc0 = __expf(m0 - nm0), p0 = __expf(t0 - nm0);
        float sc1 = __expf(m1 - nm1), p1 = __expf(t1 - nm1);
        m0 = nm0; m1 = nm1;
        l0 = l0 * sc0 + p0;
        l1 = l1 * sc1 + p1;
        A0.x = A0.x * sc0 + p0 * va0.x;  A1.x = A1.x * sc1 + p1 * va1.x;
        A0.y = A0.y * sc0 + p0 * va0.y;  A1.y = A1.y * sc1 + p1 * va1.y;
        A0.z = A0.z * sc0 + p0 * vb0.x;  A1.z = A1.z * sc1 + p1 * vb1.x;
        A0.w = A0.w * sc0 + p0 * vb0.y;  A1.w = A1.w * sc1 + p1 * vb1.y;
    }
    if (e < end) {
        int s0 = __ldg(&g_esrc[e]);
        uint4 kv0 = *(const uint4*)&g_kv[s0 * 256 + lane * 8];
        float2 ka0 = __half22float2(*(__half2*)&kv0.x);
        float2 kb0 = __half22float2(*(__half2*)&kv0.y);
        float t0 = q4.x * ka0.x + q4.y * ka0.y + q4.z * kb0.x + q4.w * kb0.y;
        t0 += __shfl_xor_sync(0xffffffffu, t0, 1);
        t0 += __shfl_xor_sync(0xffffffffu, t0, 2);
        t0 += __shfl_xor_sync(0xffffffffu, t0, 4);
        float2 va0 = __half22float2(*(__half2*)&kv0.z);
        float2 vb0 = __half22float2(*(__half2*)&kv0.w);
        float nm0 = fmaxf(m0, t0);
        float sc0 = __expf(m0 - nm0), p0 = __expf(t0 - nm0);
        m0 = nm0;
        l0 = l0 * sc0 + p0;
        A0.x = A0.x * sc0 + p0 * va0.x;
        A0.y = A0.y * sc0 + p0 * va0.y;
        A0.z = A0.z * sc0 + p0 * vb0.x;
        A0.w = A0.w * sc0 + p0 * vb0.y;
    }

    // merge the two states
    float nm = fmaxf(m0, m1);
    float s0 = __expf(m0 - nm), s1 = __expf(m1 - nm);
    float l = l0 * s0 + l1 * s1;
    float4 acc;
    acc.x = A0.x * s0 + A1.x * s1;
    acc.y = A0.y * s0 + A1.y * s1;
    acc.z = A0.z * s0 + A1.z * s1;
    acc.w = A0.w * s0 + A1.w * s1;

    if (l > 0.f) {
        float r = 1.f / l;
        float4 o = *(float4*)&g_sk[base + off];
        o.x += acc.x * r;
        o.y += acc.y * r;
        o.z += acc.z * r;
        o.w += acc.w * r;
        *(float4*)&g_sk[base + off] = o;
    }
}

// ---------------- launch (fork-join: CSR chain || BN+GEMM chain) ----------------
extern "C" void kernel_launch(void* const* d_in, const int* in_sizes, int n_in,
                              void* d_out, int out_size) {
    const float* x         = (const float*)d_in[0];
    const void* ei         = d_in[1];
    const float* bn_gamma  = (const float*)d_in[2];
    const float* bn_beta   = (const float*)d_in[3];
    const float* Wq        = (const float*)d_in[4];
    const float* bq        = (const float*)d_in[5];
    const float* Wk        = (const float*)d_in[6];
    const float* bk        = (const float*)d_in[7];
    const float* Wv        = (const float*)d_in[8];
    const float* bv        = (const float*)d_in[9];
    const float* Wskip     = (const float*)d_in[10];
    const float* bskip     = (const float*)d_in[11];
    const float* Wfc       = (const float*)d_in[12];
    const float* bfc       = (const float*)d_in[13];
    float* out = (float*)d_out;

    static cudaStream_t s_side = nullptr;
    static cudaEvent_t ev_fork = nullptr, ev_join = nullptr;
    if (s_side == nullptr) {
        cudaStreamCreateWithFlags(&s_side, cudaStreamNonBlocking);
        cudaEventCreateWithFlags(&ev_fork, cudaEventDisableTiming);
        cudaEventCreateWithFlags(&ev_join, cudaEventDisableTiming);
    }

    const int SMEM = (128 * LDA + 128 * LDW) * 4;  // 137216 B
    cudaFuncSetAttribute(gemm_qkvs_fused_k, cudaFuncAttributeMaxDynamicSharedMemorySize, SMEM);
    cudaFuncSetAttribute(gemm_final_k, cudaFuncAttributeMaxDynamicSharedMemorySize, SMEM);

    const int MBLK = (NN + 127) / 128; // 782

    init_k<<<256, 256>>>();

    // fork: CSR chain on side stream (detect only feeds hist/scatter)
    cudaEventRecord(ev_fork, 0);
    cudaStreamWaitEvent(s_side, ev_fork, 0);
    detect_k<<<1, 32, 0, s_side>>>((const long long*)ei);
    hist_k<<<(NE + 255) / 256, 256, 0, s_side>>>(ei);
    block_scan_k<<<NB, 1024, 0, s_side>>>();
    scan_totals_k<<<1, 128, 0, s_side>>>();
    add_offsets_k<<<NB, 1024, 0, s_side>>>();
    scatter_k<<<(NE + 255) / 256, 256, 0, s_side>>>(ei);
    cudaEventRecord(ev_join, s_side);

    // main chain: BN + fused QKVS GEMM
    bn_stats_k<<<512, 128>>>(x);
    bn_finalize_k<<<1, 128>>>(bn_gamma, bn_beta);
    gemm_qkvs_fused_k<<<MBLK, 256, SMEM>>>(x, Wq, bq, Wk, bk, Wv, bv, Wskip, bskip);

    // join: attention needs CSR + q/kv/skip
    cudaStreamWaitEvent(0, ev_join, 0);
    attn_k<<<(NN * 32 + 255) / 256, 256>>>();
    gemm_final_k<<<MBLK, 256, SMEM>>>(Wfc, bfc, x, out);
}

// round 10
// speedup vs baseline: 2.2737x; 1.0144x over previous
#include <cuda_runtime.h>
#include <cuda_fp16.h>
#include <math.h>
#include <stdint.h>

#define NN 100000
#define NE 1600000
#define CH 128          // channels = H*D
#define NH 4
#define HD 32
#define EPS 1e-5f
#define NB 98           // ceil(NN/1024) scan blocks

// ---------------- scratch (device globals; no allocation allowed) ----------------
__device__ __align__(128) float g_q[NN * CH];
__device__ __align__(128) __half g_kv[NN * 2 * CH];  // per node: 32 chunks of [4 half k | 4 half v]
__device__ __align__(128) float g_sk[NN * CH];   // skip, then conv (in-place)
__device__ __align__(128) float g_stats[4 * CH]; // sum, sumsq, scale, shift
__device__ __align__(128) float g_wt[5 * CH * CH]; // tf32-prerounded Wq,Wk,Wv,Wskip,Wfc
__device__ int g_cnt[NN];
__device__ int g_rowptr[NN + 1];
__device__ int g_cursor[NN];
__device__ int g_esrc[NE];
__device__ int g_blksum[128];
__device__ int g_blkoff[128];
__device__ int g_is64;

// ---------------- edge dtype detection (one warp, parallel) ----------------
__global__ void detect_k(const long long* __restrict__ ei) {
    int lane = threadIdx.x;
    int bad = 0;
    #pragma unroll
    for (int i = 0; i < 8; i++) {
        long long v = ei[lane + i * 32];
        bad |= (v < 0 || v >= NN) ? 1 : 0;
    }
    bad = __any_sync(0xffffffffu, bad);
    if (lane == 0) g_is64 = !bad;
}

__device__ __forceinline__ int edge_at(const void* ei, int idx) {
    return g_is64 ? (int)((const long long*)ei)[idx] : ((const int*)ei)[idx];
}

// ---------------- tf32 helpers ----------------
__device__ __forceinline__ float tf32r(float x) {
    uint32_t u;
    asm("cvt.rna.tf32.f32 %0, %1;" : "=r"(u) : "f"(x));
    return __uint_as_float(u);
}

// pre-round all 5 weight matrices to tf32 (keeps RNA precision on the cp.async path)
__global__ void prep_w_k(const float* __restrict__ Wq, const float* __restrict__ Wk,
                         const float* __restrict__ Wv, const float* __restrict__ Ws,
                         const float* __restrict__ Wfc) {
    int i = blockIdx.x * blockDim.x + threadIdx.x;   // float4 index, total 5*4096
    if (i < 5 * 4096) {
        int m = i >> 12, idx = i & 4095;
        const float* src;
        switch (m) {
            case 0: src = Wq; break;
            case 1: src = Wk; break;
            case 2: src = Wv; break;
            case 3: src = Ws; break;
            default: src = Wfc; break;
        }
        float4 w = ((const float4*)src)[idx];
        w.x = tf32r(w.x); w.y = tf32r(w.y); w.z = tf32r(w.z); w.w = tf32r(w.w);
        ((float4*)g_wt)[m * 4096 + idx] = w;
    }
}

// ---------------- init ----------------
__global__ void init_k() {
    int i = blockIdx.x * blockDim.x + threadIdx.x;
    if (i < 2 * CH) g_stats[i] = 0.f;
    for (int j = i; j < NN; j += gridDim.x * blockDim.x) g_cnt[j] = 0;
}

// ---------------- batchnorm stats ----------------
__global__ void bn_stats_k(const float* __restrict__ x) {
    int c = threadIdx.x; // 128 threads
    float s = 0.f, sq = 0.f;
    for (int r = blockIdx.x; r < NN; r += gridDim.x) {
        float v = x[r * CH + c];
        s += v; sq += v * v;
    }
    atomicAdd(&g_stats[c], s);
    atomicAdd(&g_stats[CH + c], sq);
}

__global__ void bn_finalize_k(const float* __restrict__ gamma, const float* __restrict__ beta) {
    int c = threadIdx.x;
    float mean = g_stats[c] / (float)NN;
    float var = g_stats[CH + c] / (float)NN - mean * mean;
    float scale = gamma[c] * rsqrtf(var + EPS);
    g_stats[2 * CH + c] = scale;
    g_stats[3 * CH + c] = beta[c] - mean * scale;
}

// ---------------- CSR build ----------------
__global__ void hist_k(const void* __restrict__ ei) {
    int e = blockIdx.x * blockDim.x + threadIdx.x;
    if (e < NE) {
        int d = edge_at(ei, NE + e);
        if (d >= 0 && d < NN) atomicAdd(&g_cnt[d], 1);
    }
}

__global__ void block_scan_k() {
    __shared__ int warpsum[32];
    int t = threadIdx.x, lane = t & 31, wid = t >> 5;
    int i = blockIdx.x * 1024 + t;
    int v = (i < NN) ? g_cnt[i] : 0;
    int x = v;
    #pragma unroll
    for (int o = 1; o < 32; o <<= 1) {
        int y = __shfl_up_sync(0xffffffffu, x, o);
        if (lane >= o) x += y;
    }
    if (lane == 31) warpsum[wid] = x;
    __syncthreads();
    if (wid == 0) {
        int w = warpsum[lane];
        #pragma unroll
        for (int o = 1; o < 32; o <<= 1) {
            int y = __shfl_up_sync(0xffffffffu, w, o);
            if (lane >= o) w += y;
        }
        warpsum[lane] = w;
    }
    __syncthreads();
    int prefix = (wid > 0) ? warpsum[wid - 1] : 0;
    int incl = x + prefix;
    if (i < NN) g_rowptr[i] = incl - v;
    if (t == 1023) g_blksum[blockIdx.x] = incl;
}

__global__ void scan_totals_k() {
    __shared__ int warpsum[4];
    int t = threadIdx.x, lane = t & 31, wid = t >> 5; // 128 threads
    int v = (t < NB) ? g_blksum[t] : 0;
    int x = v;
    #pragma unroll
    for (int o = 1; o < 32; o <<= 1) {
        int y = __shfl_up_sync(0xffffffffu, x, o);
        if (lane >= o) x += y;
    }
    if (lane == 31) warpsum[wid] = x;
    __syncthreads();
    if (t == 0) {
        int a = 0;
        #pragma unroll
        for (int k = 0; k < 4; k++) { int b = warpsum[k]; warpsum[k] = a; a += b; }
        g_rowptr[NN] = a;
    }
    __syncthreads();
    if (t < NB) g_blkoff[t] = x - v + warpsum[wid];
}

__global__ void add_offsets_k() {
    int i = blockIdx.x * 1024 + threadIdx.x;
    if (i < NN) {
        int val = g_rowptr[i] + g_blkoff[blockIdx.x];
        g_rowptr[i] = val;
        g_cursor[i] = val;
    }
}

__global__ void scatter_k(const void* __restrict__ ei) {
    int e = blockIdx.x * blockDim.x + threadIdx.x;
    if (e < NE) {
        int d = edge_at(ei, NE + e);
        int s = edge_at(ei, e);
        if (d >= 0 && d < NN && s >= 0 && s < NN) {
            int pos = atomicAdd(&g_cursor[d], 1);
            if (pos >= 0 && pos < NE) g_esrc[pos] = s;
        }
    }
}

// ---------------- tf32 tensor-core GEMM ----------------
#define LDA 132
#define LDW 136

__device__ __forceinline__ void mma_tf32(float* c, const uint32_t* a, uint32_t b0, uint32_t b1) {
    asm volatile(
        "mma.sync.aligned.m16n8k8.row.col.f32.tf32.tf32.f32 "
        "{%0,%1,%2,%3}, {%4,%5,%6,%7}, {%8,%9}, {%0,%1,%2,%3};"
        : "+f"(c[0]), "+f"(c[1]), "+f"(c[2]), "+f"(c[3])
        : "r"(c ? a[0] : 0u), "r"(a[1]), "r"(a[2]), "r"(a[3]), "r"(b0), "r"(b1));
}

__device__ __forceinline__ void cp16(uint32_t smem_dst, const void* gsrc) {
    asm volatile("cp.async.ca.shared.global [%0], [%1], 16;" :: "r"(smem_dst), "l"(gsrc));
}
__device__ __forceinline__ void cp_commit() { asm volatile("cp.async.commit_group;"); }
template <int N>
__device__ __forceinline__ void cp_wait() { asm volatile("cp.async.wait_group %0;" :: "n"(N)); }

// issue cp.async staging of one 128x128 tf32 weight tile into Wbuf
__device__ __forceinline__ void stage_w_async(const float* __restrict__ Wsrc, uint32_t wbuf_u32, int t) {
    #pragma unroll
    for (int i = 0; i < 16; i++) {
        int lin = i * 256 + t;
        int r = lin >> 5, c4 = lin & 31;
        cp16(wbuf_u32 + (r * LDW + c4 * 4) * 4, Wsrc + lin * 4);
    }
    cp_commit();
}

// OUTMODE: 0 = fp32 plain, 1 = fp32 + residual, 2 = fp16 into g_kv (kvoff 0=k, 4=v)
template <int OUTMODE>
__device__ __forceinline__ void mma_compute_store(const float* As, const float* Ws,
                                                  const float* __restrict__ bias,
                                                  float* __restrict__ Out,
                                                  const float* __restrict__ resid,
                                                  int row0, int t, int kvoff) {
    const int lane = t & 31, wrp = t >> 5;
    const int wm = wrp & 3, wn = wrp >> 2;
    const int g = lane >> 2, tg = lane & 3;

    float acc[2][8][4];
    #pragma unroll
    for (int mi = 0; mi < 2; mi++)
        #pragma unroll
        for (int nj = 0; nj < 8; nj++)
            #pragma unroll
            for (int c = 0; c < 4; c++) acc[mi][nj][c] = 0.f;

    #pragma unroll
    for (int ks = 0; ks < 16; ks++) {
        const int k0 = ks * 8;
        uint32_t a[2][4];
        #pragma unroll
        for (int mi = 0; mi < 2; mi++) {
            const float* p = As + (wm * 32 + mi * 16 + g) * LDA + k0 + tg;
            a[mi][0] = __float_as_uint(p[0]);
            a[mi][1] = __float_as_uint(p[8 * LDA]);
            a[mi][2] = __float_as_uint(p[4]);
            a[mi][3] = __float_as_uint(p[8 * LDA + 4]);
        }
        #pragma unroll
        for (int nj = 0; nj < 8; nj++) {
            const float* qp = Ws + (k0 + tg) * LDW + wn * 64 + nj * 8 + g;
            uint32_t b0 = __float_as_uint(qp[0]);
            uint32_t b1 = __float_as_uint(qp[4 * LDW]);
            mma_tf32(acc[0][nj], a[0], b0, b1);
            mma_tf32(acc[1][nj], a[1], b0, b1);
        }
    }

    #pragma unroll
    for (int mi = 0; mi < 2; mi++) {
        #pragma unroll
        for (int half_ = 0; half_ < 2; half_++) {
            int gr = row0 + wm * 32 + mi * 16 + g + half_ * 8;
            if (gr < NN) {
                #pragma unroll
                for (int nj = 0; nj < 8; nj++) {
                    int col = wn * 64 + nj * 8 + 2 * tg;
                    float c0 = acc[mi][nj][half_ * 2 + 0] + __ldg(&bias[col]);
                    float c1 = acc[mi][nj][half_ * 2 + 1] + __ldg(&bias[col + 1]);
                    if (OUTMODE == 1) {
                        float2 rr = *(const float2*)&resid[gr * 128 + col];
                        c0 += rr.x; c1 += rr.y;
                    }
                    if (OUTMODE == 2) {
                        int addr = gr * 256 + (col >> 2) * 8 + kvoff + (col & 3);
                        *(__half2*)&g_kv[addr] = __floats2half2_rn(c0, c1);
                    } else {
                        *(float2*)&Out[gr * 128 + col] = make_float2(c0, c1);
                    }
                }
            }
        }
    }
}

// fused QKVS: stage A (BN+ReLU+tf32) once; cp.async double-buffered weights
__global__ void __launch_bounds__(256, 1) gemm_qkvs_fused_k(
    const float* __restrict__ x,
    const float* __restrict__ bq, const float* __restrict__ bk,
    const float* __restrict__ bv, const float* __restrict__ bs) {
    extern __shared__ float sm[];
    float* As = sm;
    float* Wb[2] = { sm + 128 * LDA, sm + 128 * LDA + 128 * LDW };
    uint32_t wb_u32[2] = { (uint32_t)__cvta_generic_to_shared(Wb[0]),
                           (uint32_t)__cvta_generic_to_shared(Wb[1]) };
    const int t = threadIdx.x;
    const int row0 = blockIdx.x * 128;

    // warm the pipeline: W0, W1 in flight
    stage_w_async(g_wt + 0 * 16384, wb_u32[0], t);
    stage_w_async(g_wt + 1 * 16384, wb_u32[1], t);

    // stage A with fused BN+ReLU+tf32 (overlaps with cp.async in flight)
    #pragma unroll
    for (int i = 0; i < 16; i++) {
        int lin = i * 256 + t;
        int r = lin >> 5, c4 = lin & 31;
        int gr = row0 + r;
        float4 a = (gr < NN) ? ((const float4*)x)[gr * 32 + c4] : make_float4(0.f, 0.f, 0.f, 0.f);
        float4 sc = ((const float4*)(g_stats + 2 * CH))[c4];
        float4 sh = ((const float4*)(g_stats + 3 * CH))[c4];
        a.x = tf32r(fmaxf(0.f, a.x * sc.x + sh.x));
        a.y = tf32r(fmaxf(0.f, a.y * sc.y + sh.y));
        a.z = tf32r(fmaxf(0.f, a.z * sc.z + sh.z));
        a.w = tf32r(fmaxf(0.f, a.w * sc.w + sh.w));
        *(float4*)&As[r * LDA + c4 * 4] = a;
    }

    // i=0: q (W0 in buf0)
    cp_wait<1>(); __syncthreads();
    mma_compute_store<0>(As, Wb[0], bq, g_q, nullptr, row0, t, 0);
    __syncthreads();
    // i=1: k (W1 in buf1); prefetch W2 into buf0
    stage_w_async(g_wt + 2 * 16384, wb_u32[0], t);
    cp_wait<1>(); __syncthreads();
    mma_compute_store<2>(As, Wb[1], bk, nullptr, nullptr, row0, t, 0);
    __syncthreads();
    // i=2: v (W2 in buf0); prefetch W3 into buf1
    stage_w_async(g_wt + 3 * 16384, wb_u32[1], t);
    cp_wait<1>(); __syncthreads();
    mma_compute_store<2>(As, Wb[0], bv, nullptr, nullptr, row0, t, 4);
    __syncthreads();
    // i=3: skip (W3 in buf1)
    cp_wait<0>(); __syncthreads();
    mma_compute_store<0>(As, Wb[1], bs, g_sk, nullptr, row0, t, 0);
}

__global__ void __launch_bounds__(256, 1) gemm_final_k(
    const float* __restrict__ bfc, const float* __restrict__ x, float* __restrict__ out) {
    extern __shared__ float sm[];
    float* As = sm;
    float* Ws = sm + 128 * LDA;
    uint32_t ws_u32 = (uint32_t)__cvta_generic_to_shared(Ws);
    const int t = threadIdx.x;
    const int row0 = blockIdx.x * 128;

    stage_w_async(g_wt + 4 * 16384, ws_u32, t);

    #pragma unroll
    for (int i = 0; i < 16; i++) {
        int lin = i * 256 + t;
        int r = lin >> 5, c4 = lin & 31;
        int gr = row0 + r;
        float4 a = (gr < NN) ? ((const float4*)g_sk)[gr * 32 + c4] : make_float4(0.f, 0.f, 0.f, 0.f);
        a.x = tf32r(a.x); a.y = tf32r(a.y); a.z = tf32r(a.z); a.w = tf32r(a.w);
        *(float4*)&As[r * LDA + c4 * 4] = a;
    }
    cp_wait<0>(); __syncthreads();
    mma_compute_store<1>(As, Ws, bfc, out, x, row0, t, 0);
}

// ---------------- attention: warp-per-node, dual online-softmax accumulators ----------------
__global__ void attn_k() {
    int w = (blockIdx.x * blockDim.x + threadIdx.x) >> 5;
    int lane = threadIdx.x & 31;
    if (w >= NN) return;
    const float inv = 0.17677669529663689f; // 1/sqrt(32)
    const int off = lane * 4;               // floats [4l,4l+4); head = lane>>3
    const int base = w * CH;

    float4 q4 = *(const float4*)&g_q[base + off];
    q4.x *= inv; q4.y *= inv; q4.z *= inv; q4.w *= inv;

    int beg = g_rowptr[w], end = g_rowptr[w + 1];

    float m0 = -1e30f, l0 = 0.f, m1 = -1e30f, l1 = 0.f;
    float4 A0 = make_float4(0.f, 0.f, 0.f, 0.f);
    float4 A1 = make_float4(0.f, 0.f, 0.f, 0.f);

    int e = beg;
    for (; e + 1 < end; e += 2) {
        int s0 = __ldg(&g_esrc[e]);
        int s1 = __ldg(&g_esrc[e + 1]);
        uint4 kv0 = *(const uint4*)&g_kv[s0 * 256 + lane * 8];
        uint4 kv1 = *(const uint4*)&g_kv[s1 * 256 + lane * 8];

        float2 ka0 = __half22float2(*(__half2*)&kv0.x);
        float2 kb0 = __half22float2(*(__half2*)&kv0.y);
        float2 ka1 = __half22float2(*(__half2*)&kv1.x);
        float2 kb1 = __half22float2(*(__half2*)&kv1.y);
        float t0 = q4.x * ka0.x + q4.y * ka0.y + q4.z * kb0.x + q4.w * kb0.y;
        float t1 = q4.x * ka1.x + q4.y * ka1.y + q4.z * kb1.x + q4.w * kb1.y;
        t0 += __shfl_xor_sync(0xffffffffu, t0, 1);
        t1 += __shfl_xor_sync(0xffffffffu, t1, 1);
        t0 += __shfl_xor_sync(0xffffffffu, t0, 2);
        t1 += __shfl_xor_sync(0xffffffffu, t1, 2);
        t0 += __shfl_xor_sync(0xffffffffu, t0, 4);
        t1 += __shfl_xor_sync(0xffffffffu, t1, 4);

        float2 va0 = __half22float2(*(__half2*)&kv0.z);
        float2 vb0 = __half22float2(*(__half2*)&kv0.w);
        float2 va1 = __half22float2(*(__half2*)&kv1.z);
        float2 vb1 = __half22float2(*(__half2*)&kv1.w);

        float nm0 = fmaxf(m0, t0);
        float nm1 = fmaxf(m1, t1);
        float sc0 = __expf(m0 - nm0), p0 = __expf(t0 - nm0);
        float sc1 = __expf(m1 - nm1), p1 = __expf(t1 - nm1);
        m0 = nm0; m1 = nm1;
        l0 = l0 * sc0 + p0;
        l1 = l1 * sc1 + p1;
        A0.x = A0.x * sc0 + p0 * va0.x;  A1.x = A1.x * sc1 + p1 * va1.x;
        A0.y = A0.y * sc0 + p0 * va0.y;  A1.y = A1.y * sc1 + p1 * va1.y;
        A0.z = A0.z * sc0 + p0 * vb0.x;  A1.z = A1.z * sc1 + p1 * vb1.x;
        A0.w = A0.w * sc0 + p0 * vb0.y;  A1.w = A1.w * sc1 + p1 * vb1.y;
    }
    if (e < end) {
        int s0 = __ldg(&g_esrc[e]);
        uint4 kv0 = *(const uint4*)&g_kv[s0 * 256 + lane * 8];
        float2 ka0 = __half22float2(*(__half2*)&kv0.x);
        float2 kb0 = __half22float2(*(__half2*)&kv0.y);
        float t0 = q4.x * ka0.x + q4.y * ka0.y + q4.z * kb0.x + q4.w * kb0.y;
        t0 += __shfl_xor_sync(0xffffffffu, t0, 1);
        t0 += __shfl_xor_sync(0xffffffffu, t0, 2);
        t0 += __shfl_xor_sync(0xffffffffu, t0, 4);
        float2 va0 = __half22float2(*(__half2*)&kv0.z);
        float2 vb0 = __half22float2(*(__half2*)&kv0.w);
        float nm0 = fmaxf(m0, t0);
        float sc0 = __expf(m0 - nm0), p0 = __expf(t0 - nm0);
        m0 = nm0;
        l0 = l0 * sc0 + p0;
        A0.x = A0.x * sc0 + p0 * va0.x;
        A0.y = A0.y * sc0 + p0 * va0.y;
        A0.z = A0.z * sc0 + p0 * vb0.x;
        A0.w = A0.w * sc0 + p0 * vb0.y;
    }

    float nm = fmaxf(m0, m1);
    float s0 = __expf(m0 - nm), s1 = __expf(m1 - nm);
    float l = l0 * s0 + l1 * s1;
    float4 acc;
    acc.x = A0.x * s0 + A1.x * s1;
    acc.y = A0.y * s0 + A1.y * s1;
    acc.z = A0.z * s0 + A1.z * s1;
    acc.w = A0.w * s0 + A1.w * s1;

    if (l > 0.f) {
        float r = 1.f / l;
        float4 o = *(float4*)&g_sk[base + off];
        o.x += acc.x * r;
        o.y += acc.y * r;
        o.z += acc.z * r;
        o.w += acc.w * r;
        *(float4*)&g_sk[base + off] = o;
    }
}

// ---------------- launch (fork-join: CSR chain || BN+GEMM chain) ----------------
extern "C" void kernel_launch(void* const* d_in, const int* in_sizes, int n_in,
                              void* d_out, int out_size) {
    const float* x         = (const float*)d_in[0];
    const void* ei         = d_in[1];
    const float* bn_gamma  = (const float*)d_in[2];
    const float* bn_beta   = (const float*)d_in[3];
    const float* Wq        = (const float*)d_in[4];
    const float* bq        = (const float*)d_in[5];
    const float* Wk        = (const float*)d_in[6];
    const float* bk        = (const float*)d_in[7];
    const float* Wv        = (const float*)d_in[8];
    const float* bv        = (const float*)d_in[9];
    const float* Wskip     = (const float*)d_in[10];
    const float* bskip     = (const float*)d_in[11];
    const float* Wfc       = (const float*)d_in[12];
    const float* bfc       = (const float*)d_in[13];
    float* out = (float*)d_out;

    static cudaStream_t s_side = nullptr;
    static cudaEvent_t ev_fork = nullptr, ev_join = nullptr;
    if (s_side == nullptr) {
        cudaStreamCreateWithFlags(&s_side, cudaStreamNonBlocking);
        cudaEventCreateWithFlags(&ev_fork, cudaEventDisableTiming);
        cudaEventCreateWithFlags(&ev_join, cudaEventDisableTiming);
    }

    const int SMEM_QKVS = (128 * LDA + 2 * 128 * LDW) * 4;  // 206848 B
    const int SMEM_FIN  = (128 * LDA + 128 * LDW) * 4;      // 137216 B
    cudaFuncSetAttribute(gemm_qkvs_fused_k, cudaFuncAttributeMaxDynamicSharedMemorySize, SMEM_QKVS);
    cudaFuncSetAttribute(gemm_final_k, cudaFuncAttributeMaxDynamicSharedMemorySize, SMEM_FIN);

    const int MBLK = (NN + 127) / 128; // 782

    init_k<<<256, 256>>>();
    prep_w_k<<<80, 256>>>(Wq, Wk, Wv, Wskip, Wfc);

    // fork: CSR chain on side stream
    cudaEventRecord(ev_fork, 0);
    cudaStreamWaitEvent(s_side, ev_fork, 0);
    detect_k<<<1, 32, 0, s_side>>>((const long long*)ei);
    hist_k<<<(NE + 255) / 256, 256, 0, s_side>>>(ei);
    block_scan_k<<<NB, 1024, 0, s_side>>>();
    scan_totals_k<<<1, 128, 0, s_side>>>();
    add_offsets_k<<<NB, 1024, 0, s_side>>>();
    scatter_k<<<(NE + 255) / 256, 256, 0, s_side>>>(ei);
    cudaEventRecord(ev_join, s_side);

    // main chain: BN + pipelined QKVS GEMM
    bn_stats_k<<<512, 128>>>(x);
    bn_finalize_k<<<1, 128>>>(bn_gamma, bn_beta);
    gemm_qkvs_fused_k<<<MBLK, 256, SMEM_QKVS>>>(x, bq, bk, bv, bskip);

    // join: attention needs CSR + q/kv/skip
    cudaStreamWaitEvent(0, ev_join, 0);
    attn_k<<<(NN * 32 + 255) / 256, 256>>>();
    gemm_final_k<<<MBLK, 256, SMEM_FIN>>>(bfc, x, out);
}